// round 14
// baseline (speedup 1.0000x reference)
#include <cuda_runtime.h>
#include <cuda_bf16.h>
#include <math.h>

#define BB 16
#define SS 2048
#define DD 256
#define HM 256
#define PP 8
#define CHN 16
#define CC 128
#define LL 264            // PP + 2*CC
#define NH 8
#define HD 32
#define NSEG 16
#define LD_INV (1.0f/((float)LL*(float)DD))

#define MROWS 16          // MLP kernel M-tile
#define APITCH 264        // A/H smem pitch (bf16 elems)
#define BPITCH 26         // B stage pitch (bf16 elems)
#define SMEM_MLP (4*MROWS*APITCH*2 + 2*2*256*BPITCH*2 + 2*256*4)

// ---------------- persistent scratch (device globals; no allocation) -------
__device__ __align__(16) float g_fastW1[BB*DD*HM];
__device__ __align__(16) float g_fastb1[BB*HM];
__device__ __align__(16) float g_fastW2[BB*HM*DD];
__device__ __align__(16) float g_fastb2[BB*DD];
__device__ __align__(16) float g_momW1[BB*DD*HM];
__device__ __align__(16) float g_momb1[BB*HM];
__device__ __align__(16) float g_momW2[BB*HM*DD];
__device__ __align__(16) float g_momb2[BB*DD];
__device__ __align__(16) float g_qall[BB*SS*DD];
__device__ __align__(16) float g_Wkv[DD*2*DD];
__device__ __align__(16) float g_attnA[NSEG*BB*LL*DD];
__device__ __align__(16) float g_qkv[BB*LL*3*DD];
__device__ __align__(16) float g_ao[BB*LL*DD];
__device__ __align__(16) float g_y[BB*LL*DD];
__device__ __align__(16) float g_k[BB*LL*DD];
__device__ __align__(16) float g_v[BB*LL*DD];
__device__ __align__(16) float g_s[BB*LL*HM];
__device__ __align__(16) float g_dz[BB*LL*HM];
__device__ __align__(16) float g_e[BB*LL*DD];
__device__ float g_coef[BB*3];

// ---------------- bf16 split helpers (truncation hi + rn lo) ---------------
__device__ __forceinline__ void split2(float x0, float x1, unsigned& ph, unsigned& pl) {
    unsigned b0 = __float_as_uint(x0), b1 = __float_as_uint(x1);
    ph = __byte_perm(b0, b1, 0x7632);
    float l0 = x0 - __uint_as_float(b0 & 0xFFFF0000u);
    float l1 = x1 - __uint_as_float(b1 & 0xFFFF0000u);
    __nv_bfloat162 t = __float22bfloat162_rn(make_float2(l0, l1));
    pl = *(unsigned*)&t;
}
__device__ __forceinline__ void split1(float x, __nv_bfloat16& h, __nv_bfloat16& l) {
    unsigned b = __float_as_uint(x);
    unsigned short hs = (unsigned short)(b >> 16);
    h = *reinterpret_cast<__nv_bfloat16*>(&hs);
    l = __float2bfloat16(x - __uint_as_float(b & 0xFFFF0000u));
}
#define MMA_BF16(d, a, bq) \
    asm volatile("mma.sync.aligned.m16n8k16.row.col.f32.bf16.bf16.f32 " \
        "{%0,%1,%2,%3}, {%4,%5,%6,%7}, {%8,%9}, {%0,%1,%2,%3};" \
        : "+f"(d[0]), "+f"(d[1]), "+f"(d[2]), "+f"(d[3]) \
        : "r"(a[0]), "r"(a[1]), "r"(a[2]), "r"(a[3]), "r"(bq[0]), "r"(bq[1]))

// ---------------- init: fast weights, momentum, Wkv concat -----------------
__global__ void k_init(const float* __restrict__ mW1, const float* __restrict__ mb1,
                       const float* __restrict__ mW2, const float* __restrict__ mb2,
                       const float* __restrict__ W_K, const float* __restrict__ W_V) {
    long i = (long)blockIdx.x * blockDim.x + threadIdx.x;
    if (i < (long)BB*DD*HM) {
        g_fastW1[i] = mW1[i % (DD*HM)]; g_momW1[i] = 0.f;
        g_fastW2[i] = mW2[i % (HM*DD)]; g_momW2[i] = 0.f;
    }
    if (i < BB*HM) { g_fastb1[i] = mb1[i % HM]; g_momb1[i] = 0.f; }
    if (i < BB*DD) { g_fastb2[i] = mb2[i % DD]; g_momb2[i] = 0.f; }
    if (i < DD*2*DD) {
        int k = (int)(i >> 9), n = (int)(i & 511);
        g_Wkv[i] = (n < DD) ? W_K[k*DD + n] : W_V[k*DD + n - DD];
    }
}

// ---------------- prepack pers + x slices for ALL segments -----------------
__global__ void k_prepack(const float* __restrict__ x, const float* __restrict__ pers) {
    long i = (long)blockIdx.x * blockDim.x + threadIdx.x;
    const long TOT = (long)NSEG*BB*(PP+CC)*DD;
    if (i >= TOT) return;
    int d = (int)(i % DD);
    long t1 = i / DD;
    int t = (int)(t1 % (PP+CC));
    long t2 = t1 / (PP+CC);
    int b = (int)(t2 % BB);
    int s = (int)(t2 / BB);
    int row = (t < PP) ? t : (t + CC);
    float v = (t < PP) ? pers[t*DD + d]
                       : x[(long)b*SS*DD + (long)(s*CC + t - PP)*DD + d];
    g_attnA[(((long)s*BB + b)*LL + row)*DD + d] = v;
}

// ---------------- fused memory-MLP body (16-row tiles) ---------------------
// mode 0: O1 = silu(A@W1+b1)@W2+b2
// mode 1: z=A@W1+b1; s=silu(z)->O1; e=(s@W2+b2-v)*LD_INV->O2; dz=(e@W2^T)*silu'(z)->O3
// mode 2: O1 = (silu(A@W1+b1)@W2+b2) * A
// mode 3: y=A@Wx^T+bx ->O1 (+smem); k=y@Wy[:,0:256]->O2; v=y@Wy[:,256:512]->O3
__device__ __forceinline__ void mlp_body(
    int mode, const float* Ain, float* O1, float* O2, float* O3,
    const float* Vin, const float* Wx, const float* Wy, const float* bx,
    int b, int m0, int M, int lda, long sA, long sO1)
{
    extern __shared__ __align__(16) char smraw[];
    __nv_bfloat16* Ah  = (__nv_bfloat16*)smraw;
    __nv_bfloat16* Al  = Ah + MROWS*APITCH;
    __nv_bfloat16* Hh  = Al + MROWS*APITCH;
    __nv_bfloat16* Hl  = Hh + MROWS*APITCH;
    __nv_bfloat16* BsH = Hl + MROWS*APITCH;         // [2][256][BPITCH]
    __nv_bfloat16* BsL = BsH + 2*256*BPITCH;
    float* biasS = (float*)(BsL + 2*256*BPITCH);    // [2][256]

    int tid = threadIdx.x;
    Ain += (long)b * sA;
    O1  += (long)b * sO1;
    if (mode == 1 || mode == 3) {
        O2 += (long)b * (long)LL*DD;
        O3 += (long)b * (long)LL*DD;
    }
    if (mode == 1) Vin += (long)b * (long)LL*DD;

    if (mode == 3) {
        biasS[tid]       = bx[tid];
        biasS[256 + tid] = 0.f;
    } else {
        biasS[tid]       = g_fastb1[b*HM + tid];
        biasS[256 + tid] = g_fastb2[b*DD + tid];
    }

    // stage A (16 x 256) split into Ah/Al
    #pragma unroll
    for (int j = 0; j < 4; j++) {
        int f = tid + j*256;
        int r = f >> 6, c4 = (f & 63) * 4;
        int rr = m0 + r; if (rr >= M) rr = M - 1;
        float4 v = *(const float4*)(Ain + (long)rr*lda + c4);
        unsigned ph0, pl0, ph1, pl1;
        split2(v.x, v.y, ph0, pl0); split2(v.z, v.w, ph1, pl1);
        *(unsigned*)&Ah[r*APITCH + c4]     = ph0;
        *(unsigned*)&Ah[r*APITCH + c4 + 2] = ph1;
        *(unsigned*)&Al[r*APITCH + c4]     = pl0;
        *(unsigned*)&Al[r*APITCH + c4 + 2] = pl1;
    }
    __syncthreads();

    int warp = tid >> 5, lane = tid & 31;
    int wn = warp;                         // 8 warps x 32 cols, 16 rows
    int g = lane >> 2, tq = lane & 3;
    float acc[4][4];
    float vv0[16], vv1[16];

    auto loadB = [&](const float* W, int ldw, int tb, int kt, float* vv) {
        if (tb) {
            const float* p = W + (long)tid*ldw + kt*16;
            #pragma unroll
            for (int j = 0; j < 4; j++) {
                float4 t4 = *(const float4*)(p + j*4);
                vv[j*4]=t4.x; vv[j*4+1]=t4.y; vv[j*4+2]=t4.z; vv[j*4+3]=t4.w;
            }
        } else {
            const float* p = W + (long)(kt*16)*ldw + tid;
            #pragma unroll
            for (int k = 0; k < 16; k++) vv[k] = p[(long)k*ldw];
        }
    };
    auto storeB = [&](int buf, const float* vv) {
        __nv_bfloat16* dh = BsH + (buf*256 + tid)*BPITCH;
        __nv_bfloat16* dl = BsL + (buf*256 + tid)*BPITCH;
        #pragma unroll
        for (int k = 0; k < 16; k += 2) {
            unsigned ph, pl;
            split2(vv[k], vv[k+1], ph, pl);
            *(unsigned*)&dh[k] = ph;
            *(unsigned*)&dl[k] = pl;
        }
    };
    auto mma_tile = [&](const __nv_bfloat16* Xh, const __nv_bfloat16* Xl, int kt) {
        int cur = kt & 1;
        int ko = kt*16 + tq*2;
        unsigned ah[4], al[4];
        ah[0] = *(const unsigned*)&Xh[g*APITCH + ko];
        ah[1] = *(const unsigned*)&Xh[(g+8)*APITCH + ko];
        ah[2] = *(const unsigned*)&Xh[g*APITCH + ko + 8];
        ah[3] = *(const unsigned*)&Xh[(g+8)*APITCH + ko + 8];
        al[0] = *(const unsigned*)&Xl[g*APITCH + ko];
        al[1] = *(const unsigned*)&Xl[(g+8)*APITCH + ko];
        al[2] = *(const unsigned*)&Xl[g*APITCH + ko + 8];
        al[3] = *(const unsigned*)&Xl[(g+8)*APITCH + ko + 8];
        #pragma unroll
        for (int ni = 0; ni < 4; ni++) {
            int nr = wn*32 + ni*8 + g;
            const __nv_bfloat16* ph = BsH + (cur*256 + nr)*BPITCH + tq*2;
            const __nv_bfloat16* pl = BsL + (cur*256 + nr)*BPITCH + tq*2;
            unsigned bh[2], bl[2];
            bh[0] = *(const unsigned*)ph; bh[1] = *(const unsigned*)(ph + 8);
            bl[0] = *(const unsigned*)pl; bl[1] = *(const unsigned*)(pl + 8);
            MMA_BF16(acc[ni], ah, bh);
            MMA_BF16(acc[ni], al, bh);
            MMA_BF16(acc[ni], ah, bl);
        }
    };
    auto run_gemm = [&](const __nv_bfloat16* Xh, const __nv_bfloat16* Xl,
                        const float* W, int ldw, int tb) {
        #pragma unroll
        for (int ni = 0; ni < 4; ni++)
            #pragma unroll
            for (int e = 0; e < 4; e++) acc[ni][e] = 0.f;
        loadB(W, ldw, tb, 0, vv0);
        storeB(0, vv0);
        loadB(W, ldw, tb, 1, vv1);
        __syncthreads();
        int kt = 0;
        while (true) {
            if (kt + 2 < 16) loadB(W, ldw, tb, kt + 2, vv0);
            mma_tile(Xh, Xl, kt);
            if (kt + 1 < 16) storeB((kt + 1) & 1, vv1);
            __syncthreads();
            if (++kt >= 16) break;
            if (kt + 2 < 16) loadB(W, ldw, tb, kt + 2, vv1);
            mma_tile(Xh, Xl, kt);
            if (kt + 1 < 16) storeB((kt + 1) & 1, vv0);
            __syncthreads();
            if (++kt >= 16) break;
        }
    };

    // ---- GEMM1 ----
    if (mode == 3) run_gemm(Ah, Al, Wx, DD, 1);
    else           run_gemm(Ah, Al, g_fastW1 + (long)b*DD*HM, HM, 0);
    #pragma unroll
    for (int ni = 0; ni < 4; ni++)
    #pragma unroll
    for (int h2 = 0; h2 < 2; h2++) {
        int rl = g + h2*8;
        int c  = wn*32 + ni*8 + tq*2;
        float z0 = acc[ni][h2*2+0] + biasS[c];
        float z1 = acc[ni][h2*2+1] + biasS[c+1];
        unsigned ph, pl;
        if (mode == 3) {
            split2(z0, z1, ph, pl);
            *(unsigned*)&Hh[rl*APITCH + c] = ph;
            *(unsigned*)&Hl[rl*APITCH + c] = pl;
            if (m0 + rl < M)
                *(float2*)&O1[(long)(m0+rl)*256 + c] = make_float2(z0, z1);
        } else {
            float s0v = z0 / (1.f + expf(-z0));
            float s1v = z1 / (1.f + expf(-z1));
            split2(s0v, s1v, ph, pl);
            *(unsigned*)&Hh[rl*APITCH + c] = ph;
            *(unsigned*)&Hl[rl*APITCH + c] = pl;
            if (mode == 1) {
                split2(z0, z1, ph, pl);          // keep z (A is dead)
                *(unsigned*)&Ah[rl*APITCH + c] = ph;
                *(unsigned*)&Al[rl*APITCH + c] = pl;
                if (m0 + rl < M)
                    *(float2*)&O1[(long)(m0+rl)*256 + c] = make_float2(s0v, s1v);
            }
        }
    }
    __syncthreads();

    // ---- GEMM2 ----
    if (mode == 3) run_gemm(Hh, Hl, Wy, 2*DD, 0);
    else           run_gemm(Hh, Hl, g_fastW2 + (long)b*HM*DD, DD, 0);
    #pragma unroll
    for (int ni = 0; ni < 4; ni++)
    #pragma unroll
    for (int h2 = 0; h2 < 2; h2++) {
        int rl = g + h2*8;
        int c  = wn*32 + ni*8 + tq*2;
        float v0 = acc[ni][h2*2+0] + biasS[256 + c];
        float v1 = acc[ni][h2*2+1] + biasS[256 + c + 1];
        bool valid = (m0 + rl) < M;
        long ro = (long)(m0 + rl) * 256 + c;
        if (mode == 0) {
            if (valid) *(float2*)&O1[ro] = make_float2(v0, v1);
        } else if (mode == 2) {
            float y0 = __bfloat162float(Ah[rl*APITCH + c])   + __bfloat162float(Al[rl*APITCH + c]);
            float y1 = __bfloat162float(Ah[rl*APITCH + c+1]) + __bfloat162float(Al[rl*APITCH + c+1]);
            if (valid) *(float2*)&O1[ro] = make_float2(v0*y0, v1*y1);
        } else if (mode == 3) {
            if (valid) *(float2*)&O2[ro] = make_float2(v0, v1);   // k plane
        } else {
            float e0 = 0.f, e1 = 0.f;
            if (valid) {
                float2 vr = *(const float2*)&Vin[ro];
                e0 = (v0 - vr.x) * LD_INV;
                e1 = (v1 - vr.y) * LD_INV;
                *(float2*)&O2[ro] = make_float2(e0, e1);
            }
            unsigned ph, pl;
            split2(e0, e1, ph, pl);              // e -> H (s is dead)
            *(unsigned*)&Hh[rl*APITCH + c] = ph;
            *(unsigned*)&Hl[rl*APITCH + c] = pl;
        }
    }

    // ---- GEMM3 ----
    if (mode == 1 || mode == 3) {
        __syncthreads();
        if (mode == 3) run_gemm(Hh, Hl, Wy + DD, 2*DD, 0);
        else           run_gemm(Hh, Hl, g_fastW2 + (long)b*HM*DD, DD, 1);
        #pragma unroll
        for (int ni = 0; ni < 4; ni++)
        #pragma unroll
        for (int h2 = 0; h2 < 2; h2++) {
            int rl = g + h2*8;
            int c  = wn*32 + ni*8 + tq*2;
            if (m0 + rl < M) {
                long ro = (long)(m0 + rl) * 256 + c;
                if (mode == 3) {
                    *(float2*)&O3[ro] = make_float2(acc[ni][h2*2+0], acc[ni][h2*2+1]);  // v plane
                } else {
                    float z0 = __bfloat162float(Ah[rl*APITCH + c])   + __bfloat162float(Al[rl*APITCH + c]);
                    float z1 = __bfloat162float(Ah[rl*APITCH + c+1]) + __bfloat162float(Al[rl*APITCH + c+1]);
                    float sg0 = 1.f/(1.f+expf(-z0)), sg1 = 1.f/(1.f+expf(-z1));
                    float d0 = acc[ni][h2*2+0] * sg0 * (1.f + z0*(1.f - sg0));
                    float d1 = acc[ni][h2*2+1] * sg1 * (1.f + z1*(1.f - sg1));
                    *(float2*)&O3[ro] = make_float2(d0, d1);
                }
            }
        }
    }
}

__global__ __launch_bounds__(256) void k_mlp_single(
    int mode, const float* Ain, float* O1, float* O2, float* O3,
    const float* Vin, const float* Wx, const float* Wy, const float* bx,
    int M, int lda, long sA, long sO1)
{
    mlp_body(mode, Ain, O1, O2, O3, Vin, Wx, Wy, bx,
             blockIdx.z, blockIdx.y*MROWS, M, lda, sA, sO1);
}

// dual launch: z<BB -> mode2 (gated out, seg s); z>=BB -> mode0 (h, seg s+1)
__global__ __launch_bounds__(256) void k_mlp_dual(
    const float* A2, float* O2out, const float* A0, float* O0out,
    long sA2, long sO2, long sA0, long sO0)
{
    int z = blockIdx.z;
    if (z < BB) mlp_body(2, A2, O2out, nullptr, nullptr, nullptr, nullptr, nullptr, nullptr,
                         z, blockIdx.y*MROWS, CC, DD, sA2, sO2);
    else        mlp_body(0, A0, O0out, nullptr, nullptr, nullptr, nullptr, nullptr, nullptr,
                         z - BB, blockIdx.y*MROWS, CC, DD, sA0, sO0);
}

#define KP 24

// ---------------- tensor-core GEMM (bf16x3), 64x64 tile, pipelined ---------
// A is [M][K].  TB: B is [N][K]; else [K][N].  K % 16 == 0, K >= 32.
template<bool TB, bool BIAS>
__global__ __launch_bounds__(256) void t_gemm(
        const float* __restrict__ A, const float* __restrict__ Bw,
        const float* __restrict__ bias, float* __restrict__ C,
        int M, int N, int K, int lda, int ldb, int ldc,
        long sA, long sB, long sC, int sBias) {
    __shared__ __align__(16) __nv_bfloat16 AsH[2][64][KP];
    __shared__ __align__(16) __nv_bfloat16 AsL[2][64][KP];
    __shared__ __align__(16) __nv_bfloat16 BsH[2][64][KP];
    __shared__ __align__(16) __nv_bfloat16 BsL[2][64][KP];
    int b = blockIdx.z;
    A  += (long)b * sA;
    Bw += (long)b * sB;
    C  += (long)b * sC;
    if (BIAS) bias += (long)b * sBias;
    int tid = threadIdx.x;
    int n0 = blockIdx.x * 64, m0 = blockIdx.y * 64;
    int nkt = K >> 4;

    int am  = tid >> 2, akq = (tid & 3) * 4;
    int bkr = tid >> 4, bnq = (tid & 15) * 4;
    int bn  = tid >> 2, bkq = (tid & 3) * 4;

    int r0 = m0 + am; if (r0 >= M) r0 = M - 1;
    const float* Aptr = A + (long)r0*lda;

    auto readAr = [&](int kt, float* ar) {
        float4 v = *(const float4*)(Aptr + kt*16 + akq);
        ar[0]=v.x; ar[1]=v.y; ar[2]=v.z; ar[3]=v.w;
    };
    auto readBr = [&](int kt, float* br) {
        if (!TB) {
            float4 v = *(const float4*)(Bw + (long)(kt*16 + bkr)*ldb + n0 + bnq);
            br[0]=v.x; br[1]=v.y; br[2]=v.z; br[3]=v.w;
        } else {
            float4 v = *(const float4*)(Bw + (long)(n0+bn)*ldb + kt*16 + bkq);
            br[0]=v.x; br[1]=v.y; br[2]=v.z; br[3]=v.w;
        }
    };
    auto storeAr = [&](int buf, const float* ar) {
        unsigned ph0, pl0, ph1, pl1;
        split2(ar[0], ar[1], ph0, pl0);
        split2(ar[2], ar[3], ph1, pl1);
        *(unsigned*)&AsH[buf][am][akq]   = ph0;
        *(unsigned*)&AsH[buf][am][akq+2] = ph1;
        *(unsigned*)&AsL[buf][am][akq]   = pl0;
        *(unsigned*)&AsL[buf][am][akq+2] = pl1;
    };
    auto storeBr = [&](int buf, const float* br) {
        if (!TB) {
            #pragma unroll
            for (int j = 0; j < 4; j++) {
                __nv_bfloat16 h, l;
                split1(br[j], h, l);
                BsH[buf][bnq+j][bkr] = h;
                BsL[buf][bnq+j][bkr] = l;
            }
        } else {
            unsigned ph0, pl0, ph1, pl1;
            split2(br[0], br[1], ph0, pl0);
            split2(br[2], br[3], ph1, pl1);
            *(unsigned*)&BsH[buf][bn][bkq]   = ph0;
            *(unsigned*)&BsH[buf][bn][bkq+2] = ph1;
            *(unsigned*)&BsL[buf][bn][bkq]   = pl0;
            *(unsigned*)&BsL[buf][bn][bkq+2] = pl1;
        }
    };

    int warp = tid >> 5, lane = tid & 31;
    int wm = warp & 1, wn = warp >> 1;
    int g = lane >> 2, tq = lane & 3;
    int ko = tq * 2;
    float acc[2][2][4] = {};

    auto mma_on = [&](int cur) {
        unsigned ah[2][4], al[2][4], bh[2][2], bl[2][2];
        #pragma unroll
        for (int mi = 0; mi < 2; mi++) {
            int r = wm*32 + mi*16 + g;
            ah[mi][0] = *(const unsigned*)&AsH[cur][r][ko];
            ah[mi][1] = *(const unsigned*)&AsH[cur][r+8][ko];
            ah[mi][2] = *(const unsigned*)&AsH[cur][r][ko+8];
            ah[mi][3] = *(const unsigned*)&AsH[cur][r+8][ko+8];
            al[mi][0] = *(const unsigned*)&AsL[cur][r][ko];
            al[mi][1] = *(const unsigned*)&AsL[cur][r+8][ko];
            al[mi][2] = *(const unsigned*)&AsL[cur][r][ko+8];
            al[mi][3] = *(const unsigned*)&AsL[cur][r+8][ko+8];
        }
        #pragma unroll
        for (int ni = 0; ni < 2; ni++) {
            int nr = wn*16 + ni*8 + g;
            bh[ni][0] = *(const unsigned*)&BsH[cur][nr][ko];
            bh[ni][1] = *(const unsigned*)&BsH[cur][nr][ko+8];
            bl[ni][0] = *(const unsigned*)&BsL[cur][nr][ko];
            bl[ni][1] = *(const unsigned*)&BsL[cur][nr][ko+8];
        }
        #pragma unroll
        for (int mi = 0; mi < 2; mi++)
            #pragma unroll
            for (int ni = 0; ni < 2; ni++) {
                MMA_BF16(acc[mi][ni], ah[mi], bh[ni]);
                MMA_BF16(acc[mi][ni], al[mi], bh[ni]);
                MMA_BF16(acc[mi][ni], ah[mi], bl[ni]);
            }
    };

    float a0[4], b0r[4], a1[4], b1r[4];
    readAr(0, a0); readBr(0, b0r);
    storeAr(0, a0); storeBr(0, b0r);
    readAr(1, a1); readBr(1, b1r);
    __syncthreads();
    int kt = 0;
    while (true) {
        if (kt + 2 < nkt) { readAr(kt+2, a0); readBr(kt+2, b0r); }
        mma_on(kt & 1);
        if (kt + 1 < nkt) { storeAr((kt+1) & 1, a1); storeBr((kt+1) & 1, b1r); }
        __syncthreads();
        if (++kt >= nkt) break;
        if (kt + 2 < nkt) { readAr(kt+2, a1); readBr(kt+2, b1r); }
        mma_on(kt & 1);
        if (kt + 1 < nkt) { storeAr((kt+1) & 1, a0); storeBr((kt+1) & 1, b0r); }
        __syncthreads();
        if (++kt >= nkt) break;
    }

    #pragma unroll
    for (int mi = 0; mi < 2; mi++) {
        #pragma unroll
        for (int ni = 0; ni < 2; ni++) {
            int c0 = n0 + wn*16 + ni*8 + tq*2;
            float bv0 = 0.f, bv1 = 0.f;
            if (BIAS) { bv0 = bias[c0]; bv1 = bias[c0+1]; }
            #pragma unroll
            for (int h2 = 0; h2 < 2; h2++) {
                int r = m0 + wm*32 + mi*16 + g + h2*8;
                if (r < M) {
                    C[(long)r*ldc + c0]   = acc[mi][ni][h2*2+0] + bv0;
                    C[(long)r*ldc + c0+1] = acc[mi][ni][h2*2+1] + bv1;
                }
            }
        }
    }
}

// ---------------- fused grad GEMM + momentum/decay update ------------------
// z<16: gW2 tile = s^T e, update fastW2/momW2 (+b2 via colsum e)
// z>=16: gW1 tile = k^T dz, update fastW1/momW1 (+b1 via colsum dz)
__global__ __launch_bounds__(256) void k_grad() {
    __shared__ __align__(16) __nv_bfloat16 AsH[2][64][KP];
    __shared__ __align__(16) __nv_bfloat16 AsL[2][64][KP];
    __shared__ __align__(16) __nv_bfloat16 BsH[2][64][KP];
    __shared__ __align__(16) __nv_bfloat16 BsL[2][64][KP];
    int z = blockIdx.z;
    int b = z & (BB-1);
    bool sel = z >= BB;
    const float *A, *B;
    float *fp, *mp, *fbp, *mbp;
    int lda, ldb;
    if (!sel) {
        A = g_s + (long)b*LL*HM;   B = g_e  + (long)b*LL*DD;
        fp = g_fastW2 + (long)b*HM*DD; mp = g_momW2 + (long)b*HM*DD;
        fbp = g_fastb2 + b*DD; mbp = g_momb2 + b*DD;
        lda = HM; ldb = DD;
    } else {
        A = g_k + (long)b*LL*DD;   B = g_dz + (long)b*LL*HM;
        fp = g_fastW1 + (long)b*DD*HM; mp = g_momW1 + (long)b*DD*HM;
        fbp = g_fastb1 + b*HM; mbp = g_momb1 + b*HM;
        lda = DD; ldb = HM;
    }
    const int K = LL, nkt = 17;
    int tid = threadIdx.x;
    int n0 = blockIdx.x * 64, m0 = blockIdx.y * 64;

    int akr = tid >> 4, amq = (tid & 15) * 4;
    int bkr = tid >> 4, bnq = (tid & 15) * 4;

    auto readAr = [&](int kt, float* ar) {
        int kr = kt*16 + akr;
        if (kr < K) {
            float4 v = *(const float4*)(A + (long)kr*lda + m0 + amq);
            ar[0]=v.x; ar[1]=v.y; ar[2]=v.z; ar[3]=v.w;
        } else { ar[0]=ar[1]=ar[2]=ar[3]=0.f; }
    };
    auto readBr = [&](int kt, float* br) {
        int kr = kt*16 + bkr;
        if (kr < K) {
            float4 v = *(const float4*)(B + (long)kr*ldb + n0 + bnq);
            br[0]=v.x; br[1]=v.y; br[2]=v.z; br[3]=v.w;
        } else { br[0]=br[1]=br[2]=br[3]=0.f; }
    };
    auto storeAr = [&](int buf, const float* ar) {
        #pragma unroll
        for (int j = 0; j < 4; j++) {
            __nv_bfloat16 h, l;
            split1(ar[j], h, l);
            AsH[buf][amq+j][akr] = h;
            AsL[buf][amq+j][akr] = l;
        }
    };
    auto storeBr = [&](int buf, const float* br) {
        #pragma unroll
        for (int j = 0; j < 4; j++) {
            __nv_bfloat16 h, l;
            split1(br[j], h, l);
            BsH[buf][bnq+j][bkr] = h;
            BsL[buf][bnq+j][bkr] = l;
        }
    };

    int warp = tid >> 5, lane = tid & 31;
    int wm = warp & 1, wn = warp >> 1;
    int g = lane >> 2, tq = lane & 3;
    int ko = tq * 2;
    float acc[2][2][4] = {};
    float csum = 0.f;

    auto mma_on = [&](int cur) {
        unsigned ah[2][4], al[2][4], bh[2][2], bl[2][2];
        #pragma unroll
        for (int mi = 0; mi < 2; mi++) {
            int r = wm*32 + mi*16 + g;
            ah[mi][0] = *(const unsigned*)&AsH[cur][r][ko];
            ah[mi][1] = *(const unsigned*)&AsH[cur][r+8][ko];
            ah[mi][2] = *(const unsigned*)&AsH[cur][r][ko+8];
            ah[mi][3] = *(const unsigned*)&AsH[cur][r+8][ko+8];
            al[mi][0] = *(const unsigned*)&AsL[cur][r][ko];
            al[mi][1] = *(const unsigned*)&AsL[cur][r+8][ko];
            al[mi][2] = *(const unsigned*)&AsL[cur][r][ko+8];
            al[mi][3] = *(const unsigned*)&AsL[cur][r+8][ko+8];
        }
        #pragma unroll
        for (int ni = 0; ni < 2; ni++) {
            int nr = wn*16 + ni*8 + g;
            bh[ni][0] = *(const unsigned*)&BsH[cur][nr][ko];
            bh[ni][1] = *(const unsigned*)&BsH[cur][nr][ko+8];
            bl[ni][0] = *(const unsigned*)&BsL[cur][nr][ko];
            bl[ni][1] = *(const unsigned*)&BsL[cur][nr][ko+8];
        }
        if (tid < 64) {
            #pragma unroll
            for (int k2 = 0; k2 < 16; k2 += 2) {
                float2 hf = __bfloat1622float2(*(const __nv_bfloat162*)&BsH[cur][tid][k2]);
                float2 lf = __bfloat1622float2(*(const __nv_bfloat162*)&BsL[cur][tid][k2]);
                csum += hf.x + hf.y + lf.x + lf.y;
            }
        }
        #pragma unroll
        for (int mi = 0; mi < 2; mi++)
            #pragma unroll
            for (int ni = 0; ni < 2; ni++) {
                MMA_BF16(acc[mi][ni], ah[mi], bh[ni]);
                MMA_BF16(acc[mi][ni], al[mi], bh[ni]);
                MMA_BF16(acc[mi][ni], ah[mi], bl[ni]);
            }
    };

    float a0[4], b0r[4], a1[4], b1r[4];
    readAr(0, a0); readBr(0, b0r);
    storeAr(0, a0); storeBr(0, b0r);
    readAr(1, a1); readBr(1, b1r);
    __syncthreads();
    int kt = 0;
    while (true) {
        if (kt + 2 < nkt) { readAr(kt+2, a0); readBr(kt+2, b0r); }
        mma_on(kt & 1);
        if (kt + 1 < nkt) { storeAr((kt+1) & 1, a1); storeBr((kt+1) & 1, b1r); }
        __syncthreads();
        if (++kt >= nkt) break;
        if (kt + 2 < nkt) { readAr(kt+2, a1); readBr(kt+2, b1r); }
        mma_on(kt & 1);
        if (kt + 1 < nkt) { storeAr((kt+1) & 1, a0); storeBr((kt+1) & 1, b0r); }
        __syncthreads();
        if (++kt >= nkt) break;
    }

    float alpha = g_coef[b*3+0], eta = g_coef[b*3+1], theta = g_coef[b*3+2];

    if (blockIdx.y == 0 && tid < 64) {
        int idx = n0 + tid;
        float m = eta * mbp[idx] - theta * csum;
        mbp[idx] = m;
        fbp[idx] = (1.f - alpha) * fbp[idx] + m;
    }

    #pragma unroll
    for (int mi = 0; mi < 2; mi++)
        #pragma unroll
        for (int ni = 0; ni < 2; ni++) {
            int c0 = n0 + wn*16 + ni*8 + tq*2;
            #pragma unroll
            for (int h2 = 0; h2 < 2; h2++) {
                int r = m0 + wm*32 + mi*16 + g + h2*8;
                long i0 = (long)r*256 + c0;
                float m0v = eta * mp[i0]   - theta * acc[mi][ni][h2*2+0];
                float m1v = eta * mp[i0+1] - theta * acc[mi][ni][h2*2+1];
                mp[i0]   = m0v;
                mp[i0+1] = m1v;
                fp[i0]   = (1.f - alpha) * fp[i0]   + m0v;
                fp[i0+1] = (1.f - alpha) * fp[i0+1] + m1v;
            }
        }
}

// ---------------- attention: block = (b, head, 8-row tile), smem K/V -------
__global__ void k_attn2() {
    __shared__ float Ks[64][33];
    __shared__ float Vs[64][33];
    __shared__ float qs[8][32];
    __shared__ float ps[8][32];
    int blk = blockIdx.x;
    int tile = blk % (LL/8);
    int hh = (blk / (LL/8)) % NH;
    int b  = blk / ((LL/8)*NH);
    int rt0 = tile * 8;
    int tid = threadIdx.x;
    int w = tid >> 5, lane = tid & 31;
    int r = rt0 + w;
    const float* base = g_qkv + (long)b*LL*3*DD;
    qs[w][lane] = base[(long)r*3*DD + hh*HD + lane] * 0.17677669529663687f;
    float m = -1e30f, l = 0.f, o = 0.f;
    int ntile = (rt0 + 71) >> 6;
    int krow = tid >> 3;
    int kc = (tid & 7) * 4;
    for (int jt = 0; jt < ntile; jt++) {
        int j0 = jt * 64;
        __syncthreads();
        #pragma unroll
        for (int half = 0; half < 2; half++) {
            int jl = krow + half*32;
            int jg = j0 + jl; if (jg > LL-1) jg = LL-1;
            const float* kp = base + (long)jg*3*DD + DD + hh*HD + kc;
            float4 k4 = *(const float4*)kp;
            float4 v4 = *(const float4*)(kp + DD);
            Ks[jl][kc]=k4.x; Ks[jl][kc+1]=k4.y; Ks[jl][kc+2]=k4.z; Ks[jl][kc+3]=k4.w;
            Vs[jl][kc]=v4.x; Vs[jl][kc+1]=v4.y; Vs[jl][kc+2]=v4.z; Vs[jl][kc+3]=v4.w;
        }
        __syncthreads();
        #pragma unroll
        for (int c = 0; c < 2; c++) {
            int jbase = j0 + c*32;
            if (jbase > r) break;
            int jl = c*32 + lane;
            int jg = jbase + lane;
            float sc = 0.f;
            #pragma unroll
            for (int d = 0; d < 32; d++) sc += qs[w][d] * Ks[jl][d];
            if (jg > r) sc = -1e30f;
            float cm = sc;
            #pragma unroll
            for (int s = 16; s; s >>= 1) cm = fmaxf(cm, __shfl_xor_sync(0xffffffffu, cm, s));
            float mn = fmaxf(m, cm);
            float p = (jg <= r) ? expf(sc - mn) : 0.f;
            __syncwarp();
            ps[w][lane] = p;
            float psum = p;
            #pragma unroll
            for (int s = 16; s; s >>= 1) psum += __shfl_xor_sync(0xffffffffu, psum, s);
            float corr = expf(m - mn);
            l = l*corr + psum; o *= corr; m = mn;
            __syncwarp();
            int jmax = min(32, r - jbase + 1);
            for (int jj = 0; jj < jmax; jj++)
                o += ps[w][jj] * Vs[c*32 + jj][lane];
        }
    }
    g_ao[((long)b*LL + r)*DD + hh*HD + lane] = o / l;
}

// ---------------- gate coefficients ----------------------------------------
__global__ void k_coef(const float* __restrict__ cW1, const float* __restrict__ cb1,
                       const float* __restrict__ cW2, const float* __restrict__ cb2) {
    int b = blockIdx.x, tid = threadIdx.x;
    __shared__ float ybar[DD];
    __shared__ float ch[CHN];
    float sum = 0.f;
    const float* yp = g_y + (long)b*LL*DD + tid;
    for (int t = 0; t < LL; t++) sum += yp[(long)t*DD];
    ybar[tid] = sum / (float)LL;
    __syncthreads();
    if (tid < CHN) {
        float a = cb1[tid];
        for (int d = 0; d < DD; d++) a += ybar[d] * cW1[d*CHN + tid];
        ch[tid] = a / (1.f + expf(-a));
    }
    __syncthreads();
    if (tid < 3) {
        float a = cb2[tid];
        for (int j = 0; j < CHN; j++) a += ch[j] * cW2[j*3 + tid];
        g_coef[b*3 + tid] = 1.f / (1.f + expf(-a));
    }
}

// ---------------------------------------------------------------------------
extern "C" void kernel_launch(void* const* d_in, const int* in_sizes, int n_in,
                              void* d_out, int out_size) {
    const float* x     = (const float*)d_in[0];
    const float* pers  = (const float*)d_in[1];
    const float* W_Q   = (const float*)d_in[2];
    const float* in_w  = (const float*)d_in[3];
    const float* in_b  = (const float*)d_in[4];
    const float* out_w = (const float*)d_in[5];
    const float* out_b = (const float*)d_in[6];
    const float* mW1   = (const float*)d_in[7];
    const float* mb1   = (const float*)d_in[8];
    const float* mW2   = (const float*)d_in[9];
    const float* mb2   = (const float*)d_in[10];
    const float* W_K   = (const float*)d_in[11];
    const float* W_V   = (const float*)d_in[12];
    const float* cW1   = (const float*)d_in[13];
    const float* cb1   = (const float*)d_in[14];
    const float* cW2   = (const float*)d_in[15];
    const float* cb2   = (const float*)d_in[16];
    float* out = (float*)d_out;

    cudaFuncSetAttribute(k_mlp_single, cudaFuncAttributeMaxDynamicSharedMemorySize, SMEM_MLP);
    cudaFuncSetAttribute(k_mlp_dual,   cudaFuncAttributeMaxDynamicSharedMemorySize, SMEM_MLP);

    float *pQall, *pWkv, *pAttnA, *pQkv, *pAo, *pY, *pK, *pV, *pS, *pDz, *pE;
    cudaGetSymbolAddress((void**)&pQall, g_qall);
    cudaGetSymbolAddress((void**)&pWkv, g_Wkv);
    cudaGetSymbolAddress((void**)&pAttnA, g_attnA);
    cudaGetSymbolAddress((void**)&pQkv, g_qkv);
    cudaGetSymbolAddress((void**)&pAo, g_ao);
    cudaGetSymbolAddress((void**)&pY, g_y);
    cudaGetSymbolAddress((void**)&pK, g_k);
    cudaGetSymbolAddress((void**)&pV, g_v);
    cudaGetSymbolAddress((void**)&pS, g_s);
    cudaGetSymbolAddress((void**)&pDz, g_dz);
    cudaGetSymbolAddress((void**)&pE, g_e);

    k_init<<<((long)BB*DD*HM + 255)/256, 256>>>(mW1, mb1, mW2, mb2, W_K, W_V);
    k_prepack<<<((long)NSEG*BB*(PP+CC)*DD + 255)/256, 256>>>(x, pers);

    // Q_all = x @ W_Q  (M = 32768)
    t_gemm<false,false><<<dim3(DD/64, (BB*SS)/64, 1), 256>>>(
        x, W_Q, nullptr, pQall, BB*SS, DD, DD, DD, DD, DD, 0L, 0L, 0L, 0);

    // h(0) = silu(q(0) @ W1 + b1) @ W2 + b2
    k_mlp_single<<<dim3(1, CC/MROWS, BB), 256, SMEM_MLP>>>(
        0, pQall, pAttnA + PP*DD, nullptr, nullptr, nullptr, nullptr, nullptr, nullptr,
        CC, DD, (long)SS*DD, (long)LL*DD);

    const int LT = (LL + MROWS - 1) / MROWS;   // 17
    for (int s = 0; s < NSEG; s++) {
        int s0 = s * CC;
        float* pAttnS = pAttnA + (long)s*BB*LL*DD;

        // qkv = attn_in @ in_proj_w^T + in_proj_b  (M = 4224)
        t_gemm<true,true><<<dim3((3*DD)/64, (BB*LL)/64, 1), 256>>>(
            pAttnS, in_w, in_b, pQkv, BB*LL, 3*DD, DD, DD, DD, 3*DD, 0L, 0L, 0L, 0);
        k_attn2<<<BB*NH*(LL/8), 256>>>();

        // fused: y = ao @ out_w^T + out_b; k = y@Wkv[:,:256]; v = y@Wkv[:,256:]
        k_mlp_single<<<dim3(1, LT, BB), 256, SMEM_MLP>>>(
            3, pAo, pY, pK, pV, nullptr, out_w, pWkv, out_b,
            LL, DD, (long)LL*DD, (long)LL*DD);
        k_coef<<<BB, 256>>>(cW1, cb1, cW2, cb2);

        // fused grad: z, s, e, dz
        k_mlp_single<<<dim3(1, LT, BB), 256, SMEM_MLP>>>(
            1, pK, pS, pE, pDz, pV, nullptr, nullptr, nullptr,
            LL, DD, (long)LL*DD, (long)LL*HM);

        // gW2/gW1 tiles + fused momentum/decay weight update
        k_grad<<<dim3(4, 4, 2*BB), 256>>>();

        if (s < NSEG-1) {
            // fused: out(s) = y_last * mem_apply(y_last)  AND  h(s+1)
            k_mlp_dual<<<dim3(1, CC/MROWS, 2*BB), 256, SMEM_MLP>>>(
                pY + (long)(PP+CC)*DD, out + (long)s0*DD,
                pQall + (long)(s0+CC)*DD, pAttnA + (long)(s+1)*BB*LL*DD + PP*DD,
                (long)LL*DD, (long)SS*DD, (long)SS*DD, (long)LL*DD);
        } else {
            k_mlp_single<<<dim3(1, CC/MROWS, BB), 256, SMEM_MLP>>>(
                2, pY + (long)(PP+CC)*DD, out + (long)s0*DD, nullptr, nullptr, nullptr,
                nullptr, nullptr, nullptr, CC, DD, (long)LL*DD, (long)SS*DD);
        }
    }
}

// round 15
// speedup vs baseline: 1.0394x; 1.0394x over previous
#include <cuda_runtime.h>
#include <cuda_bf16.h>
#include <math.h>

#define BB 16
#define SS 2048
#define DD 256
#define HM 256
#define PP 8
#define CHN 16
#define CC 128
#define LL 264            // PP + 2*CC
#define NH 8
#define HD 32
#define NSEG 16
#define LD_INV (1.0f/((float)LL*(float)DD))

#define MROWS 16          // MLP kernel M-tile
#define APITCH 264        // A/H smem pitch (bf16 elems)
#define BPITCH 26         // B stage pitch (bf16 elems)
#define SMEM_MLP (4*MROWS*APITCH*2 + 2*2*256*BPITCH*2 + 2*256*4)

// ---------------- persistent scratch (device globals; no allocation) -------
__device__ __align__(16) float g_fastW1[BB*DD*HM];
__device__ __align__(16) float g_fastb1[BB*HM];
__device__ __align__(16) float g_fastW2[BB*HM*DD];
__device__ __align__(16) float g_fastb2[BB*DD];
__device__ __align__(16) float g_momW1[BB*DD*HM];
__device__ __align__(16) float g_momb1[BB*HM];
__device__ __align__(16) float g_momW2[BB*HM*DD];
__device__ __align__(16) float g_momb2[BB*DD];
__device__ __align__(16) float g_qall[BB*SS*DD];
__device__ __align__(16) float g_Wkv[DD*2*DD];
__device__ __align__(16) float g_attnA[NSEG*BB*LL*DD];
__device__ __align__(16) float g_qkv[BB*LL*3*DD];
__device__ __align__(16) float g_ao[BB*LL*DD];
__device__ __align__(16) float g_y[BB*LL*DD];
__device__ __align__(16) float g_kv[BB*LL*2*DD];
__device__ __align__(16) float g_s[BB*LL*HM];
__device__ __align__(16) float g_dz[BB*LL*HM];
__device__ __align__(16) float g_e[BB*LL*DD];
__device__ float g_coef[BB*3];

// ---------------- bf16 split helpers (truncation hi + rn lo) ---------------
__device__ __forceinline__ void split2(float x0, float x1, unsigned& ph, unsigned& pl) {
    unsigned b0 = __float_as_uint(x0), b1 = __float_as_uint(x1);
    ph = __byte_perm(b0, b1, 0x7632);
    float l0 = x0 - __uint_as_float(b0 & 0xFFFF0000u);
    float l1 = x1 - __uint_as_float(b1 & 0xFFFF0000u);
    __nv_bfloat162 t = __float22bfloat162_rn(make_float2(l0, l1));
    pl = *(unsigned*)&t;
}
__device__ __forceinline__ void split1(float x, __nv_bfloat16& h, __nv_bfloat16& l) {
    unsigned b = __float_as_uint(x);
    unsigned short hs = (unsigned short)(b >> 16);
    h = *reinterpret_cast<__nv_bfloat16*>(&hs);
    l = __float2bfloat16(x - __uint_as_float(b & 0xFFFF0000u));
}
#define MMA_BF16(d, a, bq) \
    asm volatile("mma.sync.aligned.m16n8k16.row.col.f32.bf16.bf16.f32 " \
        "{%0,%1,%2,%3}, {%4,%5,%6,%7}, {%8,%9}, {%0,%1,%2,%3};" \
        : "+f"(d[0]), "+f"(d[1]), "+f"(d[2]), "+f"(d[3]) \
        : "r"(a[0]), "r"(a[1]), "r"(a[2]), "r"(a[3]), "r"(bq[0]), "r"(bq[1]))

// ---------------- init: fast weights, momentum, Wkv concat -----------------
__global__ void k_init(const float* __restrict__ mW1, const float* __restrict__ mb1,
                       const float* __restrict__ mW2, const float* __restrict__ mb2,
                       const float* __restrict__ W_K, const float* __restrict__ W_V) {
    long i = (long)blockIdx.x * blockDim.x + threadIdx.x;
    if (i < (long)BB*DD*HM) {
        g_fastW1[i] = mW1[i % (DD*HM)]; g_momW1[i] = 0.f;
        g_fastW2[i] = mW2[i % (HM*DD)]; g_momW2[i] = 0.f;
    }
    if (i < BB*HM) { g_fastb1[i] = mb1[i % HM]; g_momb1[i] = 0.f; }
    if (i < BB*DD) { g_fastb2[i] = mb2[i % DD]; g_momb2[i] = 0.f; }
    if (i < DD*2*DD) {
        int k = (int)(i >> 9), n = (int)(i & 511);
        g_Wkv[i] = (n < DD) ? W_K[k*DD + n] : W_V[k*DD + n - DD];
    }
}

// ---------------- prepack pers + x slices for ALL segments -----------------
__global__ void k_prepack(const float* __restrict__ x, const float* __restrict__ pers) {
    long i = (long)blockIdx.x * blockDim.x + threadIdx.x;
    const long TOT = (long)NSEG*BB*(PP+CC)*DD;
    if (i >= TOT) return;
    int d = (int)(i % DD);
    long t1 = i / DD;
    int t = (int)(t1 % (PP+CC));
    long t2 = t1 / (PP+CC);
    int b = (int)(t2 % BB);
    int s = (int)(t2 / BB);
    int row = (t < PP) ? t : (t + CC);
    float v = (t < PP) ? pers[t*DD + d]
                       : x[(long)b*SS*DD + (long)(s*CC + t - PP)*DD + d];
    g_attnA[(((long)s*BB + b)*LL + row)*DD + d] = v;
}

// ---------------- fused memory-MLP body (16-row tiles) ---------------------
// mode 0: O1 = silu(A@W1+b1)@W2+b2
// mode 1: z=A@W1+b1; s=silu(z)->O1; e=(s@W2+b2-v)*LD_INV->O2; dz=(e@W2^T)*silu'(z)->O3
//         (A = k plane of interleaved kv, lda=2*DD; Vin = v plane, stride 2*DD)
// mode 2: O1 = (silu(A@W1+b1)@W2+b2) * A
__device__ __forceinline__ void mlp_body(
    int mode, const float* Ain, float* O1, float* O2, float* O3,
    const float* Vin, int b, int m0, int M, int lda, long sA, long sO1)
{
    extern __shared__ __align__(16) char smraw[];
    __nv_bfloat16* Ah  = (__nv_bfloat16*)smraw;
    __nv_bfloat16* Al  = Ah + MROWS*APITCH;
    __nv_bfloat16* Hh  = Al + MROWS*APITCH;
    __nv_bfloat16* Hl  = Hh + MROWS*APITCH;
    __nv_bfloat16* BsH = Hl + MROWS*APITCH;         // [2][256][BPITCH]
    __nv_bfloat16* BsL = BsH + 2*256*BPITCH;
    float* biasS = (float*)(BsL + 2*256*BPITCH);    // [2][256]

    int tid = threadIdx.x;
    const float* W1 = g_fastW1 + (long)b*DD*HM;
    const float* W2 = g_fastW2 + (long)b*HM*DD;
    Ain += (long)b * sA;
    O1  += (long)b * sO1;
    if (mode == 1) {
        O2  += (long)b * (long)LL*DD;
        O3  += (long)b * (long)LL*HM;
        Vin += (long)b * (long)LL*2*DD;
    }

    biasS[tid]       = g_fastb1[b*HM + tid];
    biasS[256 + tid] = g_fastb2[b*DD + tid];

    // stage A (16 x 256) split into Ah/Al
    #pragma unroll
    for (int j = 0; j < 4; j++) {
        int f = tid + j*256;
        int r = f >> 6, c4 = (f & 63) * 4;
        int rr = m0 + r; if (rr >= M) rr = M - 1;
        float4 v = *(const float4*)(Ain + (long)rr*lda + c4);
        unsigned ph0, pl0, ph1, pl1;
        split2(v.x, v.y, ph0, pl0); split2(v.z, v.w, ph1, pl1);
        *(unsigned*)&Ah[r*APITCH + c4]     = ph0;
        *(unsigned*)&Ah[r*APITCH + c4 + 2] = ph1;
        *(unsigned*)&Al[r*APITCH + c4]     = pl0;
        *(unsigned*)&Al[r*APITCH + c4 + 2] = pl1;
    }
    __syncthreads();

    int warp = tid >> 5, lane = tid & 31;
    int wn = warp;                         // 8 warps x 32 cols, 16 rows
    int g = lane >> 2, tq = lane & 3;
    float acc[4][4];
    float vv0[16], vv1[16];

    auto loadB = [&](const float* W, int ldw, int tb, int kt, float* vv) {
        if (tb) {
            const float* p = W + (long)tid*ldw + kt*16;
            #pragma unroll
            for (int j = 0; j < 4; j++) {
                float4 t4 = *(const float4*)(p + j*4);
                vv[j*4]=t4.x; vv[j*4+1]=t4.y; vv[j*4+2]=t4.z; vv[j*4+3]=t4.w;
            }
        } else {
            const float* p = W + (long)(kt*16)*ldw + tid;
            #pragma unroll
            for (int k = 0; k < 16; k++) vv[k] = p[(long)k*ldw];
        }
    };
    auto storeB = [&](int buf, const float* vv) {
        __nv_bfloat16* dh = BsH + (buf*256 + tid)*BPITCH;
        __nv_bfloat16* dl = BsL + (buf*256 + tid)*BPITCH;
        #pragma unroll
        for (int k = 0; k < 16; k += 2) {
            unsigned ph, pl;
            split2(vv[k], vv[k+1], ph, pl);
            *(unsigned*)&dh[k] = ph;
            *(unsigned*)&dl[k] = pl;
        }
    };
    auto mma_tile = [&](const __nv_bfloat16* Xh, const __nv_bfloat16* Xl, int kt) {
        int cur = kt & 1;
        int ko = kt*16 + tq*2;
        unsigned ah[4], al[4];
        ah[0] = *(const unsigned*)&Xh[g*APITCH + ko];
        ah[1] = *(const unsigned*)&Xh[(g+8)*APITCH + ko];
        ah[2] = *(const unsigned*)&Xh[g*APITCH + ko + 8];
        ah[3] = *(const unsigned*)&Xh[(g+8)*APITCH + ko + 8];
        al[0] = *(const unsigned*)&Xl[g*APITCH + ko];
        al[1] = *(const unsigned*)&Xl[(g+8)*APITCH + ko];
        al[2] = *(const unsigned*)&Xl[g*APITCH + ko + 8];
        al[3] = *(const unsigned*)&Xl[(g+8)*APITCH + ko + 8];
        #pragma unroll
        for (int ni = 0; ni < 4; ni++) {
            int nr = wn*32 + ni*8 + g;
            const __nv_bfloat16* ph = BsH + (cur*256 + nr)*BPITCH + tq*2;
            const __nv_bfloat16* pl = BsL + (cur*256 + nr)*BPITCH + tq*2;
            unsigned bh[2], bl[2];
            bh[0] = *(const unsigned*)ph; bh[1] = *(const unsigned*)(ph + 8);
            bl[0] = *(const unsigned*)pl; bl[1] = *(const unsigned*)(pl + 8);
            MMA_BF16(acc[ni], ah, bh);
            MMA_BF16(acc[ni], al, bh);
            MMA_BF16(acc[ni], ah, bl);
        }
    };
    auto run_gemm = [&](const __nv_bfloat16* Xh, const __nv_bfloat16* Xl,
                        const float* W, int ldw, int tb) {
        #pragma unroll
        for (int ni = 0; ni < 4; ni++)
            #pragma unroll
            for (int e = 0; e < 4; e++) acc[ni][e] = 0.f;
        loadB(W, ldw, tb, 0, vv0);
        storeB(0, vv0);
        loadB(W, ldw, tb, 1, vv1);
        __syncthreads();
        int kt = 0;
        while (true) {
            if (kt + 2 < 16) loadB(W, ldw, tb, kt + 2, vv0);
            mma_tile(Xh, Xl, kt);
            if (kt + 1 < 16) storeB((kt + 1) & 1, vv1);
            __syncthreads();
            if (++kt >= 16) break;
            if (kt + 2 < 16) loadB(W, ldw, tb, kt + 2, vv1);
            mma_tile(Xh, Xl, kt);
            if (kt + 1 < 16) storeB((kt + 1) & 1, vv0);
            __syncthreads();
            if (++kt >= 16) break;
        }
    };

    // ---- GEMM1: z = A @ W1 + b1 ; h1/s = silu(z) -> H buffers ----
    run_gemm(Ah, Al, W1, HM, 0);
    #pragma unroll
    for (int ni = 0; ni < 4; ni++)
    #pragma unroll
    for (int h2 = 0; h2 < 2; h2++) {
        int rl = g + h2*8;
        int c  = wn*32 + ni*8 + tq*2;
        float z0 = acc[ni][h2*2+0] + biasS[c];
        float z1 = acc[ni][h2*2+1] + biasS[c+1];
        float s0v = z0 / (1.f + expf(-z0));
        float s1v = z1 / (1.f + expf(-z1));
        unsigned ph, pl;
        split2(s0v, s1v, ph, pl);
        *(unsigned*)&Hh[rl*APITCH + c] = ph;
        *(unsigned*)&Hl[rl*APITCH + c] = pl;
        if (mode == 1) {
            split2(z0, z1, ph, pl);              // keep z (A is dead)
            *(unsigned*)&Ah[rl*APITCH + c] = ph;
            *(unsigned*)&Al[rl*APITCH + c] = pl;
            if (m0 + rl < M)
                *(float2*)&O1[(long)(m0+rl)*256 + c] = make_float2(s0v, s1v);
        }
    }
    __syncthreads();

    // ---- GEMM2: pred = s @ W2 + b2 ----
    run_gemm(Hh, Hl, W2, DD, 0);
    #pragma unroll
    for (int ni = 0; ni < 4; ni++)
    #pragma unroll
    for (int h2 = 0; h2 < 2; h2++) {
        int rl = g + h2*8;
        int c  = wn*32 + ni*8 + tq*2;
        float v0 = acc[ni][h2*2+0] + biasS[256 + c];
        float v1 = acc[ni][h2*2+1] + biasS[256 + c + 1];
        bool valid = (m0 + rl) < M;
        long ro = (long)(m0 + rl) * 256 + c;
        if (mode == 0) {
            if (valid) *(float2*)&O1[ro] = make_float2(v0, v1);
        } else if (mode == 2) {
            float y0 = __bfloat162float(Ah[rl*APITCH + c])   + __bfloat162float(Al[rl*APITCH + c]);
            float y1 = __bfloat162float(Ah[rl*APITCH + c+1]) + __bfloat162float(Al[rl*APITCH + c+1]);
            if (valid) *(float2*)&O1[ro] = make_float2(v0*y0, v1*y1);
        } else {
            float e0 = 0.f, e1 = 0.f;
            if (valid) {
                float2 vr = *(const float2*)&Vin[(long)(m0+rl)*(2*DD) + c];
                e0 = (v0 - vr.x) * LD_INV;
                e1 = (v1 - vr.y) * LD_INV;
                *(float2*)&O2[ro] = make_float2(e0, e1);
            }
            unsigned ph, pl;
            split2(e0, e1, ph, pl);              // e -> H (s is dead)
            *(unsigned*)&Hh[rl*APITCH + c] = ph;
            *(unsigned*)&Hl[rl*APITCH + c] = pl;
        }
    }

    // ---- GEMM3 (mode 1): dz = (e @ W2^T) * silu'(z) ----
    if (mode == 1) {
        __syncthreads();
        run_gemm(Hh, Hl, W2, DD, 1);
        #pragma unroll
        for (int ni = 0; ni < 4; ni++)
        #pragma unroll
        for (int h2 = 0; h2 < 2; h2++) {
            int rl = g + h2*8;
            int c  = wn*32 + ni*8 + tq*2;
            if (m0 + rl < M) {
                float z0 = __bfloat162float(Ah[rl*APITCH + c])   + __bfloat162float(Al[rl*APITCH + c]);
                float z1 = __bfloat162float(Ah[rl*APITCH + c+1]) + __bfloat162float(Al[rl*APITCH + c+1]);
                float sg0 = 1.f/(1.f+expf(-z0)), sg1 = 1.f/(1.f+expf(-z1));
                float d0 = acc[ni][h2*2+0] * sg0 * (1.f + z0*(1.f - sg0));
                float d1 = acc[ni][h2*2+1] * sg1 * (1.f + z1*(1.f - sg1));
                *(float2*)&O3[(long)(m0+rl)*256 + c] = make_float2(d0, d1);
            }
        }
    }
}

__global__ __launch_bounds__(256) void k_mlp_single(
    int mode, const float* Ain, float* O1, float* O2, float* O3,
    const float* Vin, int M, int lda, long sA, long sO1)
{
    mlp_body(mode, Ain, O1, O2, O3, Vin, blockIdx.z, blockIdx.y*MROWS, M, lda, sA, sO1);
}

// dual launch: z<BB -> mode2 (gated out, seg s); z>=BB -> mode0 (h, seg s+1)
__global__ __launch_bounds__(256) void k_mlp_dual(
    const float* A2, float* O2out, const float* A0, float* O0out,
    long sA2, long sO2, long sA0, long sO0)
{
    int z = blockIdx.z;
    if (z < BB) mlp_body(2, A2, O2out, nullptr, nullptr, nullptr, z,      blockIdx.y*MROWS, CC, DD, sA2, sO2);
    else        mlp_body(0, A0, O0out, nullptr, nullptr, nullptr, z - BB, blockIdx.y*MROWS, CC, DD, sA0, sO0);
}

#define KP 24

// ---------------- tensor-core GEMM (bf16x3), 64x64 tile, pipelined ---------
// A is [M][K].  TB: B is [N][K]; else [K][N].  K % 16 == 0, K >= 32.
template<bool TB, bool BIAS>
__global__ __launch_bounds__(256) void t_gemm(
        const float* __restrict__ A, const float* __restrict__ Bw,
        const float* __restrict__ bias, float* __restrict__ C,
        int M, int N, int K, int lda, int ldb, int ldc,
        long sA, long sB, long sC, int sBias) {
    __shared__ __align__(16) __nv_bfloat16 AsH[2][64][KP];
    __shared__ __align__(16) __nv_bfloat16 AsL[2][64][KP];
    __shared__ __align__(16) __nv_bfloat16 BsH[2][64][KP];
    __shared__ __align__(16) __nv_bfloat16 BsL[2][64][KP];
    int b = blockIdx.z;
    A  += (long)b * sA;
    Bw += (long)b * sB;
    C  += (long)b * sC;
    if (BIAS) bias += (long)b * sBias;
    int tid = threadIdx.x;
    int n0 = blockIdx.x * 64, m0 = blockIdx.y * 64;
    int nkt = K >> 4;

    int am  = tid >> 2, akq = (tid & 3) * 4;
    int bkr = tid >> 4, bnq = (tid & 15) * 4;
    int bn  = tid >> 2, bkq = (tid & 3) * 4;

    int r0 = m0 + am; if (r0 >= M) r0 = M - 1;
    const float* Aptr = A + (long)r0*lda;

    auto readAr = [&](int kt, float* ar) {
        float4 v = *(const float4*)(Aptr + kt*16 + akq);
        ar[0]=v.x; ar[1]=v.y; ar[2]=v.z; ar[3]=v.w;
    };
    auto readBr = [&](int kt, float* br) {
        if (!TB) {
            float4 v = *(const float4*)(Bw + (long)(kt*16 + bkr)*ldb + n0 + bnq);
            br[0]=v.x; br[1]=v.y; br[2]=v.z; br[3]=v.w;
        } else {
            float4 v = *(const float4*)(Bw + (long)(n0+bn)*ldb + kt*16 + bkq);
            br[0]=v.x; br[1]=v.y; br[2]=v.z; br[3]=v.w;
        }
    };
    auto storeAr = [&](int buf, const float* ar) {
        unsigned ph0, pl0, ph1, pl1;
        split2(ar[0], ar[1], ph0, pl0);
        split2(ar[2], ar[3], ph1, pl1);
        *(unsigned*)&AsH[buf][am][akq]   = ph0;
        *(unsigned*)&AsH[buf][am][akq+2] = ph1;
        *(unsigned*)&AsL[buf][am][akq]   = pl0;
        *(unsigned*)&AsL[buf][am][akq+2] = pl1;
    };
    auto storeBr = [&](int buf, const float* br) {
        if (!TB) {
            #pragma unroll
            for (int j = 0; j < 4; j++) {
                __nv_bfloat16 h, l;
                split1(br[j], h, l);
                BsH[buf][bnq+j][bkr] = h;
                BsL[buf][bnq+j][bkr] = l;
            }
        } else {
            unsigned ph0, pl0, ph1, pl1;
            split2(br[0], br[1], ph0, pl0);
            split2(br[2], br[3], ph1, pl1);
            *(unsigned*)&BsH[buf][bn][bkq]   = ph0;
            *(unsigned*)&BsH[buf][bn][bkq+2] = ph1;
            *(unsigned*)&BsL[buf][bn][bkq]   = pl0;
            *(unsigned*)&BsL[buf][bn][bkq+2] = pl1;
        }
    };

    int warp = tid >> 5, lane = tid & 31;
    int wm = warp & 1, wn = warp >> 1;
    int g = lane >> 2, tq = lane & 3;
    int ko = tq * 2;
    float acc[2][2][4] = {};

    auto mma_on = [&](int cur) {
        unsigned ah[2][4], al[2][4], bh[2][2], bl[2][2];
        #pragma unroll
        for (int mi = 0; mi < 2; mi++) {
            int r = wm*32 + mi*16 + g;
            ah[mi][0] = *(const unsigned*)&AsH[cur][r][ko];
            ah[mi][1] = *(const unsigned*)&AsH[cur][r+8][ko];
            ah[mi][2] = *(const unsigned*)&AsH[cur][r][ko+8];
            ah[mi][3] = *(const unsigned*)&AsH[cur][r+8][ko+8];
            al[mi][0] = *(const unsigned*)&AsL[cur][r][ko];
            al[mi][1] = *(const unsigned*)&AsL[cur][r+8][ko];
            al[mi][2] = *(const unsigned*)&AsL[cur][r][ko+8];
            al[mi][3] = *(const unsigned*)&AsL[cur][r+8][ko+8];
        }
        #pragma unroll
        for (int ni = 0; ni < 2; ni++) {
            int nr = wn*16 + ni*8 + g;
            bh[ni][0] = *(const unsigned*)&BsH[cur][nr][ko];
            bh[ni][1] = *(const unsigned*)&BsH[cur][nr][ko+8];
            bl[ni][0] = *(const unsigned*)&BsL[cur][nr][ko];
            bl[ni][1] = *(const unsigned*)&BsL[cur][nr][ko+8];
        }
        #pragma unroll
        for (int mi = 0; mi < 2; mi++)
            #pragma unroll
            for (int ni = 0; ni < 2; ni++) {
                MMA_BF16(acc[mi][ni], ah[mi], bh[ni]);
                MMA_BF16(acc[mi][ni], al[mi], bh[ni]);
                MMA_BF16(acc[mi][ni], ah[mi], bl[ni]);
            }
    };

    float a0[4], b0r[4], a1[4], b1r[4];
    readAr(0, a0); readBr(0, b0r);
    storeAr(0, a0); storeBr(0, b0r);
    readAr(1, a1); readBr(1, b1r);
    __syncthreads();
    int kt = 0;
    while (true) {
        if (kt + 2 < nkt) { readAr(kt+2, a0); readBr(kt+2, b0r); }
        mma_on(kt & 1);
        if (kt + 1 < nkt) { storeAr((kt+1) & 1, a1); storeBr((kt+1) & 1, b1r); }
        __syncthreads();
        if (++kt >= nkt) break;
        if (kt + 2 < nkt) { readAr(kt+2, a1); readBr(kt+2, b1r); }
        mma_on(kt & 1);
        if (kt + 1 < nkt) { storeAr((kt+1) & 1, a0); storeBr((kt+1) & 1, b0r); }
        __syncthreads();
        if (++kt >= nkt) break;
    }

    #pragma unroll
    for (int mi = 0; mi < 2; mi++) {
        #pragma unroll
        for (int ni = 0; ni < 2; ni++) {
            int c0 = n0 + wn*16 + ni*8 + tq*2;
            float bv0 = 0.f, bv1 = 0.f;
            if (BIAS) { bv0 = bias[c0]; bv1 = bias[c0+1]; }
            #pragma unroll
            for (int h2 = 0; h2 < 2; h2++) {
                int r = m0 + wm*32 + mi*16 + g + h2*8;
                if (r < M) {
                    C[(long)r*ldc + c0]   = acc[mi][ni][h2*2+0] + bv0;
                    C[(long)r*ldc + c0+1] = acc[mi][ni][h2*2+1] + bv1;
                }
            }
        }
    }
}

// ---------------- fused grad GEMM + momentum/decay update ------------------
// z<16: gW2 tile = s^T e, update fastW2/momW2 (+b2 via colsum e)
// z>=16: gW1 tile = k^T dz, update fastW1/momW1 (+b1 via colsum dz)
__global__ __launch_bounds__(256) void k_grad() {
    __shared__ __align__(16) __nv_bfloat16 AsH[2][64][KP];
    __shared__ __align__(16) __nv_bfloat16 AsL[2][64][KP];
    __shared__ __align__(16) __nv_bfloat16 BsH[2][64][KP];
    __shared__ __align__(16) __nv_bfloat16 BsL[2][64][KP];
    int z = blockIdx.z;
    int b = z & (BB-1);
    bool sel = z >= BB;
    const float *A, *B;
    float *fp, *mp, *fbp, *mbp;
    int lda, ldb;
    if (!sel) {
        A = g_s  + (long)b*LL*HM;   B = g_e  + (long)b*LL*DD;
        fp = g_fastW2 + (long)b*HM*DD; mp = g_momW2 + (long)b*HM*DD;
        fbp = g_fastb2 + b*DD; mbp = g_momb2 + b*DD;
        lda = HM;   ldb = DD;
    } else {
        A = g_kv + (long)b*LL*2*DD; B = g_dz + (long)b*LL*HM;
        fp = g_fastW1 + (long)b*DD*HM; mp = g_momW1 + (long)b*DD*HM;
        fbp = g_fastb1 + b*HM; mbp = g_momb1 + b*HM;
        lda = 2*DD; ldb = HM;
    }
    const int K = LL, nkt = 17;
    int tid = threadIdx.x;
    int n0 = blockIdx.x * 64, m0 = blockIdx.y * 64;

    int akr = tid >> 4, amq = (tid & 15) * 4;
    int bkr = tid >> 4, bnq = (tid & 15) * 4;

    auto readAr = [&](int kt, float* ar) {
        int kr = kt*16 + akr;
        if (kr < K) {
            float4 v = *(const float4*)(A + (long)kr*lda + m0 + amq);
            ar[0]=v.x; ar[1]=v.y; ar[2]=v.z; ar[3]=v.w;
        } else { ar[0]=ar[1]=ar[2]=ar[3]=0.f; }
    };
    auto readBr = [&](int kt, float* br) {
        int kr = kt*16 + bkr;
        if (kr < K) {
            float4 v = *(const float4*)(B + (long)kr*ldb + n0 + bnq);
            br[0]=v.x; br[1]=v.y; br[2]=v.z; br[3]=v.w;
        } else { br[0]=br[1]=br[2]=br[3]=0.f; }
    };
    auto storeAr = [&](int buf, const float* ar) {
        #pragma unroll
        for (int j = 0; j < 4; j++) {
            __nv_bfloat16 h, l;
            split1(ar[j], h, l);
            AsH[buf][amq+j][akr] = h;
            AsL[buf][amq+j][akr] = l;
        }
    };
    auto storeBr = [&](int buf, const float* br) {
        #pragma unroll
        for (int j = 0; j < 4; j++) {
            __nv_bfloat16 h, l;
            split1(br[j], h, l);
            BsH[buf][bnq+j][bkr] = h;
            BsL[buf][bnq+j][bkr] = l;
        }
    };

    int warp = tid >> 5, lane = tid & 31;
    int wm = warp & 1, wn = warp >> 1;
    int g = lane >> 2, tq = lane & 3;
    int ko = tq * 2;
    float acc[2][2][4] = {};
    float csum = 0.f;

    auto mma_on = [&](int cur) {
        unsigned ah[2][4], al[2][4], bh[2][2], bl[2][2];
        #pragma unroll
        for (int mi = 0; mi < 2; mi++) {
            int r = wm*32 + mi*16 + g;
            ah[mi][0] = *(const unsigned*)&AsH[cur][r][ko];
            ah[mi][1] = *(const unsigned*)&AsH[cur][r+8][ko];
            ah[mi][2] = *(const unsigned*)&AsH[cur][r][ko+8];
            ah[mi][3] = *(const unsigned*)&AsH[cur][r+8][ko+8];
            al[mi][0] = *(const unsigned*)&AsL[cur][r][ko];
            al[mi][1] = *(const unsigned*)&AsL[cur][r+8][ko];
            al[mi][2] = *(const unsigned*)&AsL[cur][r][ko+8];
            al[mi][3] = *(const unsigned*)&AsL[cur][r+8][ko+8];
        }
        #pragma unroll
        for (int ni = 0; ni < 2; ni++) {
            int nr = wn*16 + ni*8 + g;
            bh[ni][0] = *(const unsigned*)&BsH[cur][nr][ko];
            bh[ni][1] = *(const unsigned*)&BsH[cur][nr][ko+8];
            bl[ni][0] = *(const unsigned*)&BsL[cur][nr][ko];
            bl[ni][1] = *(const unsigned*)&BsL[cur][nr][ko+8];
        }
        if (tid < 64) {
            #pragma unroll
            for (int k2 = 0; k2 < 16; k2 += 2) {
                float2 hf = __bfloat1622float2(*(const __nv_bfloat162*)&BsH[cur][tid][k2]);
                float2 lf = __bfloat1622float2(*(const __nv_bfloat162*)&BsL[cur][tid][k2]);
                csum += hf.x + hf.y + lf.x + lf.y;
            }
        }
        #pragma unroll
        for (int mi = 0; mi < 2; mi++)
            #pragma unroll
            for (int ni = 0; ni < 2; ni++) {
                MMA_BF16(acc[mi][ni], ah[mi], bh[ni]);
                MMA_BF16(acc[mi][ni], al[mi], bh[ni]);
                MMA_BF16(acc[mi][ni], ah[mi], bl[ni]);
            }
    };

    float a0[4], b0r[4], a1[4], b1r[4];
    readAr(0, a0); readBr(0, b0r);
    storeAr(0, a0); storeBr(0, b0r);
    readAr(1, a1); readBr(1, b1r);
    __syncthreads();
    int kt = 0;
    while (true) {
        if (kt + 2 < nkt) { readAr(kt+2, a0); readBr(kt+2, b0r); }
        mma_on(kt & 1);
        if (kt + 1 < nkt) { storeAr((kt+1) & 1, a1); storeBr((kt+1) & 1, b1r); }
        __syncthreads();
        if (++kt >= nkt) break;
        if (kt + 2 < nkt) { readAr(kt+2, a1); readBr(kt+2, b1r); }
        mma_on(kt & 1);
        if (kt + 1 < nkt) { storeAr((kt+1) & 1, a0); storeBr((kt+1) & 1, b0r); }
        __syncthreads();
        if (++kt >= nkt) break;
    }

    float alpha = g_coef[b*3+0], eta = g_coef[b*3+1], theta = g_coef[b*3+2];

    if (blockIdx.y == 0 && tid < 64) {
        int idx = n0 + tid;
        float m = eta * mbp[idx] - theta * csum;
        mbp[idx] = m;
        fbp[idx] = (1.f - alpha) * fbp[idx] + m;
    }

    #pragma unroll
    for (int mi = 0; mi < 2; mi++)
        #pragma unroll
        for (int ni = 0; ni < 2; ni++) {
            int c0 = n0 + wn*16 + ni*8 + tq*2;
            #pragma unroll
            for (int h2 = 0; h2 < 2; h2++) {
                int r = m0 + wm*32 + mi*16 + g + h2*8;
                long i0 = (long)r*256 + c0;
                float m0v = eta * mp[i0]   - theta * acc[mi][ni][h2*2+0];
                float m1v = eta * mp[i0+1] - theta * acc[mi][ni][h2*2+1];
                mp[i0]   = m0v;
                mp[i0+1] = m1v;
                fp[i0]   = (1.f - alpha) * fp[i0]   + m0v;
                fp[i0+1] = (1.f - alpha) * fp[i0+1] + m1v;
            }
        }
}

// ---------------- attention: block = (b, head, 8-row tile), smem K/V -------
__global__ void k_attn2() {
    __shared__ float Ks[64][33];
    __shared__ float Vs[64][33];
    __shared__ float qs[8][32];
    __shared__ float ps[8][32];
    int blk = blockIdx.x;
    int tile = blk % (LL/8);
    int hh = (blk / (LL/8)) % NH;
    int b  = blk / ((LL/8)*NH);
    int rt0 = tile * 8;
    int tid = threadIdx.x;
    int w = tid >> 5, lane = tid & 31;
    int r = rt0 + w;
    const float* base = g_qkv + (long)b*LL*3*DD;
    qs[w][lane] = base[(long)r*3*DD + hh*HD + lane] * 0.17677669529663687f;
    float m = -1e30f, l = 0.f, o = 0.f;
    int ntile = (rt0 + 71) >> 6;
    int krow = tid >> 3;
    int kc = (tid & 7) * 4;
    for (int jt = 0; jt < ntile; jt++) {
        int j0 = jt * 64;
        __syncthreads();
        #pragma unroll
        for (int half = 0; half < 2; half++) {
            int jl = krow + half*32;
            int jg = j0 + jl; if (jg > LL-1) jg = LL-1;
            const float* kp = base + (long)jg*3*DD + DD + hh*HD + kc;
            float4 k4 = *(const float4*)kp;
            float4 v4 = *(const float4*)(kp + DD);
            Ks[jl][kc]=k4.x; Ks[jl][kc+1]=k4.y; Ks[jl][kc+2]=k4.z; Ks[jl][kc+3]=k4.w;
            Vs[jl][kc]=v4.x; Vs[jl][kc+1]=v4.y; Vs[jl][kc+2]=v4.z; Vs[jl][kc+3]=v4.w;
        }
        __syncthreads();
        #pragma unroll
        for (int c = 0; c < 2; c++) {
            int jbase = j0 + c*32;
            if (jbase > r) break;
            int jl = c*32 + lane;
            int jg = jbase + lane;
            float sc = 0.f;
            #pragma unroll
            for (int d = 0; d < 32; d++) sc += qs[w][d] * Ks[jl][d];
            if (jg > r) sc = -1e30f;
            float cm = sc;
            #pragma unroll
            for (int s = 16; s; s >>= 1) cm = fmaxf(cm, __shfl_xor_sync(0xffffffffu, cm, s));
            float mn = fmaxf(m, cm);
            float p = (jg <= r) ? expf(sc - mn) : 0.f;
            __syncwarp();
            ps[w][lane] = p;
            float psum = p;
            #pragma unroll
            for (int s = 16; s; s >>= 1) psum += __shfl_xor_sync(0xffffffffu, psum, s);
            float corr = expf(m - mn);
            l = l*corr + psum; o *= corr; m = mn;
            __syncwarp();
            int jmax = min(32, r - jbase + 1);
            for (int jj = 0; jj < jmax; jj++)
                o += ps[w][jj] * Vs[c*32 + jj][lane];
        }
    }
    g_ao[((long)b*LL + r)*DD + hh*HD + lane] = o / l;
}

// ---------------- gate coefficients (1024 threads, 4-way token split) ------
__global__ void k_coef(const float* __restrict__ cW1, const float* __restrict__ cb1,
                       const float* __restrict__ cW2, const float* __restrict__ cb2) {
    int b = blockIdx.x, tid = threadIdx.x;
    __shared__ float part[4][DD];
    __shared__ float ybar[DD];
    __shared__ float ch[CHN];
    int col = tid & 255, p = tid >> 8;     // 4 partitions x 66 tokens
    const float* yp = g_y + (long)b*LL*DD + col;
    float sum = 0.f;
    for (int t = p*66; t < (p+1)*66; t++) sum += yp[(long)t*DD];
    part[p][col] = sum;
    __syncthreads();
    if (tid < DD)
        ybar[tid] = (part[0][tid] + part[1][tid] + part[2][tid] + part[3][tid]) / (float)LL;
    __syncthreads();
    if (tid < CHN) {
        float a = cb1[tid];
        for (int d = 0; d < DD; d++) a += ybar[d] * cW1[d*CHN + tid];
        ch[tid] = a / (1.f + expf(-a));
    }
    __syncthreads();
    if (tid < 3) {
        float a = cb2[tid];
        for (int j = 0; j < CHN; j++) a += ch[j] * cW2[j*3 + tid];
        g_coef[b*3 + tid] = 1.f / (1.f + expf(-a));
    }
}

// ---------------------------------------------------------------------------
extern "C" void kernel_launch(void* const* d_in, const int* in_sizes, int n_in,
                              void* d_out, int out_size) {
    const float* x     = (const float*)d_in[0];
    const float* pers  = (const float*)d_in[1];
    const float* W_Q   = (const float*)d_in[2];
    const float* in_w  = (const float*)d_in[3];
    const float* in_b  = (const float*)d_in[4];
    const float* out_w = (const float*)d_in[5];
    const float* out_b = (const float*)d_in[6];
    const float* mW1   = (const float*)d_in[7];
    const float* mb1   = (const float*)d_in[8];
    const float* mW2   = (const float*)d_in[9];
    const float* mb2   = (const float*)d_in[10];
    const float* W_K   = (const float*)d_in[11];
    const float* W_V   = (const float*)d_in[12];
    const float* cW1   = (const float*)d_in[13];
    const float* cb1   = (const float*)d_in[14];
    const float* cW2   = (const float*)d_in[15];
    const float* cb2   = (const float*)d_in[16];
    float* out = (float*)d_out;

    cudaFuncSetAttribute(k_mlp_single, cudaFuncAttributeMaxDynamicSharedMemorySize, SMEM_MLP);
    cudaFuncSetAttribute(k_mlp_dual,   cudaFuncAttributeMaxDynamicSharedMemorySize, SMEM_MLP);

    float *pQall, *pWkv, *pAttnA, *pQkv, *pAo, *pY, *pKV, *pS, *pDz, *pE;
    cudaGetSymbolAddress((void**)&pQall, g_qall);
    cudaGetSymbolAddress((void**)&pWkv, g_Wkv);
    cudaGetSymbolAddress((void**)&pAttnA, g_attnA);
    cudaGetSymbolAddress((void**)&pQkv, g_qkv);
    cudaGetSymbolAddress((void**)&pAo, g_ao);
    cudaGetSymbolAddress((void**)&pY, g_y);
    cudaGetSymbolAddress((void**)&pKV, g_kv);
    cudaGetSymbolAddress((void**)&pS, g_s);
    cudaGetSymbolAddress((void**)&pDz, g_dz);
    cudaGetSymbolAddress((void**)&pE, g_e);

    k_init<<<((long)BB*DD*HM + 255)/256, 256>>>(mW1, mb1, mW2, mb2, W_K, W_V);
    k_prepack<<<((long)NSEG*BB*(PP+CC)*DD + 255)/256, 256>>>(x, pers);

    // Q_all = x @ W_Q  (M = 32768)
    t_gemm<false,false><<<dim3(DD/64, (BB*SS)/64, 1), 256>>>(
        x, W_Q, nullptr, pQall, BB*SS, DD, DD, DD, DD, DD, 0L, 0L, 0L, 0);

    // h(0) = silu(q(0) @ W1 + b1) @ W2 + b2
    k_mlp_single<<<dim3(1, CC/MROWS, BB), 256, SMEM_MLP>>>(
        0, pQall, pAttnA + PP*DD, nullptr, nullptr, nullptr,
        CC, DD, (long)SS*DD, (long)LL*DD);

    const int LT = (LL + MROWS - 1) / MROWS;   // 17
    for (int s = 0; s < NSEG; s++) {
        int s0 = s * CC;
        float* pAttnS = pAttnA + (long)s*BB*LL*DD;

        // qkv = attn_in @ in_proj_w^T + in_proj_b  (M = 4224)
        t_gemm<true,true><<<dim3((3*DD)/64, (BB*LL)/64, 1), 256>>>(
            pAttnS, in_w, in_b, pQkv, BB*LL, 3*DD, DD, DD, DD, 3*DD, 0L, 0L, 0L, 0);
        k_attn2<<<BB*NH*(LL/8), 256>>>();
        // y = ao @ out_proj_w^T + out_proj_b
        t_gemm<true,true><<<dim3(DD/64, (BB*LL)/64, 1), 256>>>(
            pAo, out_w, out_b, pY, BB*LL, DD, DD, DD, DD, DD, 0L, 0L, 0L, 0);
        k_coef<<<BB, 1024>>>(cW1, cb1, cW2, cb2);
        // [k|v] = y @ Wkv
        t_gemm<false,false><<<dim3((2*DD)/64, (BB*LL)/64, 1), 256>>>(
            pY, pWkv, nullptr, pKV, BB*LL, 2*DD, DD, DD, 2*DD, 2*DD, 0L, 0L, 0L, 0);

        // fused grad: z, s, e, dz   (17 x 16 = 272 blocks)
        k_mlp_single<<<dim3(1, LT, BB), 256, SMEM_MLP>>>(
            1, pKV, pS, pE, pDz, pKV + DD,
            LL, 2*DD, (long)LL*2*DD, (long)LL*HM);

        // gW2/gW1 tiles + fused momentum/decay weight update (one launch)
        k_grad<<<dim3(4, 4, 2*BB), 256>>>();

        if (s < NSEG-1) {
            // fused: out(s) = y_last * mem_apply(y_last)  AND  h(s+1)
            k_mlp_dual<<<dim3(1, CC/MROWS, 2*BB), 256, SMEM_MLP>>>(
                pY + (long)(PP+CC)*DD, out + (long)s0*DD,
                pQall + (long)(s0+CC)*DD, pAttnA + (long)(s+1)*BB*LL*DD + PP*DD,
                (long)LL*DD, (long)SS*DD, (long)SS*DD, (long)LL*DD);
        } else {
            k_mlp_single<<<dim3(1, CC/MROWS, BB), 256, SMEM_MLP>>>(
                2, pY + (long)(PP+CC)*DD, out + (long)s0*DD, nullptr, nullptr, nullptr,
                CC, DD, (long)LL*DD, (long)SS*DD);
        }
    }
}

// round 16
// speedup vs baseline: 1.1050x; 1.0631x over previous
#include <cuda_runtime.h>
#include <cuda_bf16.h>
#include <math.h>

#define BB 16
#define SS 2048
#define DD 256
#define HM 256
#define PP 8
#define CHN 16
#define CC 128
#define LL 264            // PP + 2*CC
#define NH 8
#define HD 32
#define NSEG 16
#define LD_INV (1.0f/((float)LL*(float)DD))

#define MROWS 32          // MLP kernel M-tile (R13-proven)
#define APITCH 264        // A/H smem pitch (bf16 elems)
#define BPITCH 26         // B stage pitch (bf16 elems)
#define SMEM_MLP (4*MROWS*APITCH*2 + 2*2*256*BPITCH*2 + 2*256*4)

// ---------------- persistent scratch (device globals; no allocation) -------
__device__ __align__(16) float g_fastW1[BB*DD*HM];
__device__ __align__(16) float g_fastb1[BB*HM];
__device__ __align__(16) float g_fastW2[BB*HM*DD];
__device__ __align__(16) float g_fastb2[BB*DD];
__device__ __align__(16) float g_momW1[BB*DD*HM];
__device__ __align__(16) float g_momb1[BB*HM];
__device__ __align__(16) float g_momW2[BB*HM*DD];
__device__ __align__(16) float g_momb2[BB*DD];
__device__ __align__(16) float g_qall[BB*SS*DD];
__device__ __align__(16) float g_Wkv[DD*2*DD];
__device__ __align__(16) float g_attnA[NSEG*BB*LL*DD];
__device__ __align__(16) float g_qkv[BB*LL*3*DD];
__device__ __align__(16) float g_ao[BB*LL*DD];
__device__ __align__(16) float g_y[BB*LL*DD];
__device__ __align__(16) float g_kv[BB*LL*2*DD];
__device__ __align__(16) float g_s[BB*LL*HM];
__device__ __align__(16) float g_dz[BB*LL*HM];
__device__ __align__(16) float g_e[BB*LL*DD];
__device__ float g_coef[BB*3];

// ---------------- bf16 split helpers (truncation hi + rn lo) ---------------
__device__ __forceinline__ void split2(float x0, float x1, unsigned& ph, unsigned& pl) {
    unsigned b0 = __float_as_uint(x0), b1 = __float_as_uint(x1);
    ph = __byte_perm(b0, b1, 0x7632);
    float l0 = x0 - __uint_as_float(b0 & 0xFFFF0000u);
    float l1 = x1 - __uint_as_float(b1 & 0xFFFF0000u);
    __nv_bfloat162 t = __float22bfloat162_rn(make_float2(l0, l1));
    pl = *(unsigned*)&t;
}
__device__ __forceinline__ void split1(float x, __nv_bfloat16& h, __nv_bfloat16& l) {
    unsigned b = __float_as_uint(x);
    unsigned short hs = (unsigned short)(b >> 16);
    h = *reinterpret_cast<__nv_bfloat16*>(&hs);
    l = __float2bfloat16(x - __uint_as_float(b & 0xFFFF0000u));
}
#define MMA_BF16(d, a, bq) \
    asm volatile("mma.sync.aligned.m16n8k16.row.col.f32.bf16.bf16.f32 " \
        "{%0,%1,%2,%3}, {%4,%5,%6,%7}, {%8,%9}, {%0,%1,%2,%3};" \
        : "+f"(d[0]), "+f"(d[1]), "+f"(d[2]), "+f"(d[3]) \
        : "r"(a[0]), "r"(a[1]), "r"(a[2]), "r"(a[3]), "r"(bq[0]), "r"(bq[1]))

// ---------------- init: fast weights, momentum, Wkv concat -----------------
__global__ void k_init(const float* __restrict__ mW1, const float* __restrict__ mb1,
                       const float* __restrict__ mW2, const float* __restrict__ mb2,
                       const float* __restrict__ W_K, const float* __restrict__ W_V) {
    long i = (long)blockIdx.x * blockDim.x + threadIdx.x;
    if (i < (long)BB*DD*HM) {
        g_fastW1[i] = mW1[i % (DD*HM)]; g_momW1[i] = 0.f;
        g_fastW2[i] = mW2[i % (HM*DD)]; g_momW2[i] = 0.f;
    }
    if (i < BB*HM) { g_fastb1[i] = mb1[i % HM]; g_momb1[i] = 0.f; }
    if (i < BB*DD) { g_fastb2[i] = mb2[i % DD]; g_momb2[i] = 0.f; }
    if (i < DD*2*DD) {
        int k = (int)(i >> 9), n = (int)(i & 511);
        g_Wkv[i] = (n < DD) ? W_K[k*DD + n] : W_V[k*DD + n - DD];
    }
}

// ---------------- prepack pers + x slices for ALL segments -----------------
__global__ void k_prepack(const float* __restrict__ x, const float* __restrict__ pers) {
    long i = (long)blockIdx.x * blockDim.x + threadIdx.x;
    const long TOT = (long)NSEG*BB*(PP+CC)*DD;
    if (i >= TOT) return;
    int d = (int)(i % DD);
    long t1 = i / DD;
    int t = (int)(t1 % (PP+CC));
    long t2 = t1 / (PP+CC);
    int b = (int)(t2 % BB);
    int s = (int)(t2 / BB);
    int row = (t < PP) ? t : (t + CC);
    float v = (t < PP) ? pers[t*DD + d]
                       : x[(long)b*SS*DD + (long)(s*CC + t - PP)*DD + d];
    g_attnA[(((long)s*BB + b)*LL + row)*DD + d] = v;
}

// ---------------- fused memory-MLP body (32-row tiles) ---------------------
// mode 0: O1 = silu(A@W1+b1)@W2+b2
// mode 1: z=A@W1+b1; s=silu(z)->O1; e=(s@W2+b2-v)*LD_INV->O2; dz=(e@W2^T)*silu'(z)->O3
// mode 2: O1 = (silu(A@W1+b1)@W2+b2) * A
__device__ __forceinline__ void mlp_body(
    int mode, const float* Ain, float* O1, float* O2, float* O3,
    const float* Vin, int b, int m0, int M, int lda, long sA, long sO1)
{
    extern __shared__ __align__(16) char smraw[];
    __nv_bfloat16* Ah  = (__nv_bfloat16*)smraw;
    __nv_bfloat16* Al  = Ah + MROWS*APITCH;
    __nv_bfloat16* Hh  = Al + MROWS*APITCH;
    __nv_bfloat16* Hl  = Hh + MROWS*APITCH;
    __nv_bfloat16* BsH = Hl + MROWS*APITCH;         // [2][256][BPITCH]
    __nv_bfloat16* BsL = BsH + 2*256*BPITCH;
    float* biasS = (float*)(BsL + 2*256*BPITCH);    // [2][256]

    int tid = threadIdx.x;
    const float* W1 = g_fastW1 + (long)b*DD*HM;
    const float* W2 = g_fastW2 + (long)b*HM*DD;
    Ain += (long)b * sA;
    O1  += (long)b * sO1;
    if (mode == 1) {
        O2  += (long)b * (long)LL*DD;
        O3  += (long)b * (long)LL*HM;
        Vin += (long)b * (long)LL*2*DD;
    }

    biasS[tid]       = g_fastb1[b*HM + tid];
    biasS[256 + tid] = g_fastb2[b*DD + tid];

    // stage A (32 x 256) split into Ah/Al
    #pragma unroll
    for (int j = 0; j < 8; j++) {
        int f = tid + j*256;
        int r = f >> 6, c4 = (f & 63) * 4;
        int rr = m0 + r; if (rr >= M) rr = M - 1;
        float4 v = *(const float4*)(Ain + (long)rr*lda + c4);
        unsigned ph0, pl0, ph1, pl1;
        split2(v.x, v.y, ph0, pl0); split2(v.z, v.w, ph1, pl1);
        *(unsigned*)&Ah[r*APITCH + c4]     = ph0;
        *(unsigned*)&Ah[r*APITCH + c4 + 2] = ph1;
        *(unsigned*)&Al[r*APITCH + c4]     = pl0;
        *(unsigned*)&Al[r*APITCH + c4 + 2] = pl1;
    }
    __syncthreads();

    int warp = tid >> 5, lane = tid & 31;
    int wn = warp;                         // 8 warps x 32 cols, full 32 rows
    int g = lane >> 2, tq = lane & 3;
    float acc[2][4][4];
    float vv0[16], vv1[16];

    auto loadB = [&](const float* W, int ldw, int tb, int kt, float* vv) {
        if (tb) {
            const float* p = W + (long)tid*ldw + kt*16;
            #pragma unroll
            for (int j = 0; j < 4; j++) {
                float4 t4 = *(const float4*)(p + j*4);
                vv[j*4]=t4.x; vv[j*4+1]=t4.y; vv[j*4+2]=t4.z; vv[j*4+3]=t4.w;
            }
        } else {
            const float* p = W + (long)(kt*16)*ldw + tid;
            #pragma unroll
            for (int k = 0; k < 16; k++) vv[k] = p[(long)k*ldw];
        }
    };
    auto storeB = [&](int buf, const float* vv) {
        __nv_bfloat16* dh = BsH + (buf*256 + tid)*BPITCH;
        __nv_bfloat16* dl = BsL + (buf*256 + tid)*BPITCH;
        #pragma unroll
        for (int k = 0; k < 16; k += 2) {
            unsigned ph, pl;
            split2(vv[k], vv[k+1], ph, pl);
            *(unsigned*)&dh[k] = ph;
            *(unsigned*)&dl[k] = pl;
        }
    };
    auto mma_tile = [&](const __nv_bfloat16* Xh, const __nv_bfloat16* Xl, int kt) {
        int cur = kt & 1;
        int ko = kt*16 + tq*2;
        unsigned ah[2][4], al[2][4];
        #pragma unroll
        for (int mi = 0; mi < 2; mi++) {
            int r = mi*16 + g;
            ah[mi][0] = *(const unsigned*)&Xh[r*APITCH + ko];
            ah[mi][1] = *(const unsigned*)&Xh[(r+8)*APITCH + ko];
            ah[mi][2] = *(const unsigned*)&Xh[r*APITCH + ko + 8];
            ah[mi][3] = *(const unsigned*)&Xh[(r+8)*APITCH + ko + 8];
            al[mi][0] = *(const unsigned*)&Xl[r*APITCH + ko];
            al[mi][1] = *(const unsigned*)&Xl[(r+8)*APITCH + ko];
            al[mi][2] = *(const unsigned*)&Xl[r*APITCH + ko + 8];
            al[mi][3] = *(const unsigned*)&Xl[(r+8)*APITCH + ko + 8];
        }
        #pragma unroll
        for (int ni = 0; ni < 4; ni++) {
            int nr = wn*32 + ni*8 + g;
            const __nv_bfloat16* ph = BsH + (cur*256 + nr)*BPITCH + tq*2;
            const __nv_bfloat16* pl = BsL + (cur*256 + nr)*BPITCH + tq*2;
            unsigned bh[2], bl[2];
            bh[0] = *(const unsigned*)ph; bh[1] = *(const unsigned*)(ph + 8);
            bl[0] = *(const unsigned*)pl; bl[1] = *(const unsigned*)(pl + 8);
            #pragma unroll
            for (int mi = 0; mi < 2; mi++) {
                MMA_BF16(acc[mi][ni], ah[mi], bh);
                MMA_BF16(acc[mi][ni], al[mi], bh);
                MMA_BF16(acc[mi][ni], ah[mi], bl);
            }
        }
    };
    auto run_gemm = [&](const __nv_bfloat16* Xh, const __nv_bfloat16* Xl,
                        const float* W, int ldw, int tb) {
        #pragma unroll
        for (int mi = 0; mi < 2; mi++)
            #pragma unroll
            for (int ni = 0; ni < 4; ni++)
                #pragma unroll
                for (int e = 0; e < 4; e++) acc[mi][ni][e] = 0.f;
        loadB(W, ldw, tb, 0, vv0);
        storeB(0, vv0);
        loadB(W, ldw, tb, 1, vv1);
        __syncthreads();
        int kt = 0;
        while (true) {
            if (kt + 2 < 16) loadB(W, ldw, tb, kt + 2, vv0);
            mma_tile(Xh, Xl, kt);
            if (kt + 1 < 16) storeB((kt + 1) & 1, vv1);
            __syncthreads();
            if (++kt >= 16) break;
            if (kt + 2 < 16) loadB(W, ldw, tb, kt + 2, vv1);
            mma_tile(Xh, Xl, kt);
            if (kt + 1 < 16) storeB((kt + 1) & 1, vv0);
            __syncthreads();
            if (++kt >= 16) break;
        }
    };

    // ---- GEMM1: z = A @ W1 + b1 ; h1/s = silu(z) -> H buffers ----
    run_gemm(Ah, Al, W1, HM, 0);
    #pragma unroll
    for (int mi = 0; mi < 2; mi++)
    #pragma unroll
    for (int ni = 0; ni < 4; ni++)
    #pragma unroll
    for (int h2 = 0; h2 < 2; h2++) {
        int rl = mi*16 + g + h2*8;
        int c  = wn*32 + ni*8 + tq*2;
        float z0 = acc[mi][ni][h2*2+0] + biasS[c];
        float z1 = acc[mi][ni][h2*2+1] + biasS[c+1];
        float s0v = z0 / (1.f + expf(-z0));
        float s1v = z1 / (1.f + expf(-z1));
        unsigned ph, pl;
        split2(s0v, s1v, ph, pl);
        *(unsigned*)&Hh[rl*APITCH + c] = ph;
        *(unsigned*)&Hl[rl*APITCH + c] = pl;
        if (mode == 1) {
            split2(z0, z1, ph, pl);              // keep z (A is dead)
            *(unsigned*)&Ah[rl*APITCH + c] = ph;
            *(unsigned*)&Al[rl*APITCH + c] = pl;
            if (m0 + rl < M)
                *(float2*)&O1[(long)(m0+rl)*256 + c] = make_float2(s0v, s1v);
        }
    }
    __syncthreads();

    // ---- GEMM2: pred = s @ W2 + b2 ----
    run_gemm(Hh, Hl, W2, DD, 0);
    #pragma unroll
    for (int mi = 0; mi < 2; mi++)
    #pragma unroll
    for (int ni = 0; ni < 4; ni++)
    #pragma unroll
    for (int h2 = 0; h2 < 2; h2++) {
        int rl = mi*16 + g + h2*8;
        int c  = wn*32 + ni*8 + tq*2;
        float v0 = acc[mi][ni][h2*2+0] + biasS[256 + c];
        float v1 = acc[mi][ni][h2*2+1] + biasS[256 + c + 1];
        bool valid = (m0 + rl) < M;
        long ro = (long)(m0 + rl) * 256 + c;
        if (mode == 0) {
            if (valid) *(float2*)&O1[ro] = make_float2(v0, v1);
        } else if (mode == 2) {
            float y0 = __bfloat162float(Ah[rl*APITCH + c])   + __bfloat162float(Al[rl*APITCH + c]);
            float y1 = __bfloat162float(Ah[rl*APITCH + c+1]) + __bfloat162float(Al[rl*APITCH + c+1]);
            if (valid) *(float2*)&O1[ro] = make_float2(v0*y0, v1*y1);
        } else {
            float e0 = 0.f, e1 = 0.f;
            if (valid) {
                float2 vr = *(const float2*)&Vin[(long)(m0+rl)*(2*DD) + c];
                e0 = (v0 - vr.x) * LD_INV;
                e1 = (v1 - vr.y) * LD_INV;
                *(float2*)&O2[ro] = make_float2(e0, e1);
            }
            unsigned ph, pl;
            split2(e0, e1, ph, pl);              // e -> H buffers (s is dead)
            *(unsigned*)&Hh[rl*APITCH + c] = ph;
            *(unsigned*)&Hl[rl*APITCH + c] = pl;
        }
    }

    // ---- GEMM3 (mode 1): dz = (e @ W2^T) * silu'(z) ----
    if (mode == 1) {
        __syncthreads();
        run_gemm(Hh, Hl, W2, DD, 1);
        #pragma unroll
        for (int mi = 0; mi < 2; mi++)
        #pragma unroll
        for (int ni = 0; ni < 4; ni++)
        #pragma unroll
        for (int h2 = 0; h2 < 2; h2++) {
            int rl = mi*16 + g + h2*8;
            int c  = wn*32 + ni*8 + tq*2;
            if (m0 + rl < M) {
                float z0 = __bfloat162float(Ah[rl*APITCH + c])   + __bfloat162float(Al[rl*APITCH + c]);
                float z1 = __bfloat162float(Ah[rl*APITCH + c+1]) + __bfloat162float(Al[rl*APITCH + c+1]);
                float sg0 = 1.f/(1.f+expf(-z0)), sg1 = 1.f/(1.f+expf(-z1));
                float d0 = acc[mi][ni][h2*2+0] * sg0 * (1.f + z0*(1.f - sg0));
                float d1 = acc[mi][ni][h2*2+1] * sg1 * (1.f + z1*(1.f - sg1));
                *(float2*)&O3[(long)(m0+rl)*256 + c] = make_float2(d0, d1);
            }
        }
    }
}

__global__ __launch_bounds__(256) void k_mlp_single(
    int mode, const float* Ain, float* O1, float* O2, float* O3,
    const float* Vin, int M, int lda, long sA, long sO1)
{
    mlp_body(mode, Ain, O1, O2, O3, Vin, blockIdx.z, blockIdx.y*MROWS, M, lda, sA, sO1);
}

// dual launch: z<BB -> mode2 (gated out, seg s); z>=BB -> mode0 (h, seg s+1)
__global__ __launch_bounds__(256) void k_mlp_dual(
    const float* A2, float* O2out, const float* A0, float* O0out,
    long sA2, long sO2, long sA0, long sO0)
{
    int z = blockIdx.z;
    if (z < BB) mlp_body(2, A2, O2out, nullptr, nullptr, nullptr, z,      blockIdx.y*MROWS, CC, DD, sA2, sO2);
    else        mlp_body(0, A0, O0out, nullptr, nullptr, nullptr, z - BB, blockIdx.y*MROWS, CC, DD, sA0, sO0);
}

#define KP 24

// ---------------- tensor-core GEMM (bf16x3), 64x64 tile, pipelined ---------
// A is [M][K].  TB: B is [N][K]; else [K][N].  K % 16 == 0, K >= 32.
template<bool TB, bool BIAS>
__global__ __launch_bounds__(256) void t_gemm(
        const float* __restrict__ A, const float* __restrict__ Bw,
        const float* __restrict__ bias, float* __restrict__ C,
        int M, int N, int K, int lda, int ldb, int ldc,
        long sA, long sB, long sC, int sBias) {
    __shared__ __align__(16) __nv_bfloat16 AsH[2][64][KP];
    __shared__ __align__(16) __nv_bfloat16 AsL[2][64][KP];
    __shared__ __align__(16) __nv_bfloat16 BsH[2][64][KP];
    __shared__ __align__(16) __nv_bfloat16 BsL[2][64][KP];
    int b = blockIdx.z;
    A  += (long)b * sA;
    Bw += (long)b * sB;
    C  += (long)b * sC;
    if (BIAS) bias += (long)b * sBias;
    int tid = threadIdx.x;
    int n0 = blockIdx.x * 64, m0 = blockIdx.y * 64;
    int nkt = K >> 4;

    int am  = tid >> 2, akq = (tid & 3) * 4;
    int bkr = tid >> 4, bnq = (tid & 15) * 4;
    int bn  = tid >> 2, bkq = (tid & 3) * 4;

    int r0 = m0 + am; if (r0 >= M) r0 = M - 1;
    const float* Aptr = A + (long)r0*lda;

    auto readAr = [&](int kt, float* ar) {
        float4 v = *(const float4*)(Aptr + kt*16 + akq);
        ar[0]=v.x; ar[1]=v.y; ar[2]=v.z; ar[3]=v.w;
    };
    auto readBr = [&](int kt, float* br) {
        if (!TB) {
            float4 v = *(const float4*)(Bw + (long)(kt*16 + bkr)*ldb + n0 + bnq);
            br[0]=v.x; br[1]=v.y; br[2]=v.z; br[3]=v.w;
        } else {
            float4 v = *(const float4*)(Bw + (long)(n0+bn)*ldb + kt*16 + bkq);
            br[0]=v.x; br[1]=v.y; br[2]=v.z; br[3]=v.w;
        }
    };
    auto storeAr = [&](int buf, const float* ar) {
        unsigned ph0, pl0, ph1, pl1;
        split2(ar[0], ar[1], ph0, pl0);
        split2(ar[2], ar[3], ph1, pl1);
        *(unsigned*)&AsH[buf][am][akq]   = ph0;
        *(unsigned*)&AsH[buf][am][akq+2] = ph1;
        *(unsigned*)&AsL[buf][am][akq]   = pl0;
        *(unsigned*)&AsL[buf][am][akq+2] = pl1;
    };
    auto storeBr = [&](int buf, const float* br) {
        if (!TB) {
            #pragma unroll
            for (int j = 0; j < 4; j++) {
                __nv_bfloat16 h, l;
                split1(br[j], h, l);
                BsH[buf][bnq+j][bkr] = h;
                BsL[buf][bnq+j][bkr] = l;
            }
        } else {
            unsigned ph0, pl0, ph1, pl1;
            split2(br[0], br[1], ph0, pl0);
            split2(br[2], br[3], ph1, pl1);
            *(unsigned*)&BsH[buf][bn][bkq]   = ph0;
            *(unsigned*)&BsH[buf][bn][bkq+2] = ph1;
            *(unsigned*)&BsL[buf][bn][bkq]   = pl0;
            *(unsigned*)&BsL[buf][bn][bkq+2] = pl1;
        }
    };

    int warp = tid >> 5, lane = tid & 31;
    int wm = warp & 1, wn = warp >> 1;
    int g = lane >> 2, tq = lane & 3;
    int ko = tq * 2;
    float acc[2][2][4] = {};

    auto mma_on = [&](int cur) {
        unsigned ah[2][4], al[2][4], bh[2][2], bl[2][2];
        #pragma unroll
        for (int mi = 0; mi < 2; mi++) {
            int r = wm*32 + mi*16 + g;
            ah[mi][0] = *(const unsigned*)&AsH[cur][r][ko];
            ah[mi][1] = *(const unsigned*)&AsH[cur][r+8][ko];
            ah[mi][2] = *(const unsigned*)&AsH[cur][r][ko+8];
            ah[mi][3] = *(const unsigned*)&AsH[cur][r+8][ko+8];
            al[mi][0] = *(const unsigned*)&AsL[cur][r][ko];
            al[mi][1] = *(const unsigned*)&AsL[cur][r+8][ko];
            al[mi][2] = *(const unsigned*)&AsL[cur][r][ko+8];
            al[mi][3] = *(const unsigned*)&AsL[cur][r+8][ko+8];
        }
        #pragma unroll
        for (int ni = 0; ni < 2; ni++) {
            int nr = wn*16 + ni*8 + g;
            bh[ni][0] = *(const unsigned*)&BsH[cur][nr][ko];
            bh[ni][1] = *(const unsigned*)&BsH[cur][nr][ko+8];
            bl[ni][0] = *(const unsigned*)&BsL[cur][nr][ko];
            bl[ni][1] = *(const unsigned*)&BsL[cur][nr][ko+8];
        }
        #pragma unroll
        for (int mi = 0; mi < 2; mi++)
            #pragma unroll
            for (int ni = 0; ni < 2; ni++) {
                MMA_BF16(acc[mi][ni], ah[mi], bh[ni]);
                MMA_BF16(acc[mi][ni], al[mi], bh[ni]);
                MMA_BF16(acc[mi][ni], ah[mi], bl[ni]);
            }
    };

    float a0[4], b0r[4], a1[4], b1r[4];
    readAr(0, a0); readBr(0, b0r);
    storeAr(0, a0); storeBr(0, b0r);
    readAr(1, a1); readBr(1, b1r);
    __syncthreads();
    int kt = 0;
    while (true) {
        if (kt + 2 < nkt) { readAr(kt+2, a0); readBr(kt+2, b0r); }
        mma_on(kt & 1);
        if (kt + 1 < nkt) { storeAr((kt+1) & 1, a1); storeBr((kt+1) & 1, b1r); }
        __syncthreads();
        if (++kt >= nkt) break;
        if (kt + 2 < nkt) { readAr(kt+2, a1); readBr(kt+2, b1r); }
        mma_on(kt & 1);
        if (kt + 1 < nkt) { storeAr((kt+1) & 1, a0); storeBr((kt+1) & 1, b0r); }
        __syncthreads();
        if (++kt >= nkt) break;
    }

    #pragma unroll
    for (int mi = 0; mi < 2; mi++) {
        #pragma unroll
        for (int ni = 0; ni < 2; ni++) {
            int c0 = n0 + wn*16 + ni*8 + tq*2;
            float bv0 = 0.f, bv1 = 0.f;
            if (BIAS) { bv0 = bias[c0]; bv1 = bias[c0+1]; }
            #pragma unroll
            for (int h2 = 0; h2 < 2; h2++) {
                int r = m0 + wm*32 + mi*16 + g + h2*8;
                if (r < M) {
                    C[(long)r*ldc + c0]   = acc[mi][ni][h2*2+0] + bv0;
                    C[(long)r*ldc + c0+1] = acc[mi][ni][h2*2+1] + bv1;
                }
            }
        }
    }
}

// ---------------- fused grad GEMM + momentum/decay update ------------------
// z<16: gW2 tile = s^T e, update fastW2/momW2 (+b2 via colsum e)
// z>=16: gW1 tile = k^T dz, update fastW1/momW1 (+b1 via colsum dz)
__global__ __launch_bounds__(256) void k_grad() {
    __shared__ __align__(16) __nv_bfloat16 AsH[2][64][KP];
    __shared__ __align__(16) __nv_bfloat16 AsL[2][64][KP];
    __shared__ __align__(16) __nv_bfloat16 BsH[2][64][KP];
    __shared__ __align__(16) __nv_bfloat16 BsL[2][64][KP];
    int z = blockIdx.z;
    int b = z & (BB-1);
    bool sel = z >= BB;
    const float *A, *B;
    float *fp, *mp, *fbp, *mbp;
    int lda, ldb;
    if (!sel) {
        A = g_s  + (long)b*LL*HM;   B = g_e  + (long)b*LL*DD;
        fp = g_fastW2 + (long)b*HM*DD; mp = g_momW2 + (long)b*HM*DD;
        fbp = g_fastb2 + b*DD; mbp = g_momb2 + b*DD;
        lda = HM;   ldb = DD;
    } else {
        A = g_kv + (long)b*LL*2*DD; B = g_dz + (long)b*LL*HM;
        fp = g_fastW1 + (long)b*DD*HM; mp = g_momW1 + (long)b*DD*HM;
        fbp = g_fastb1 + b*HM; mbp = g_momb1 + b*HM;
        lda = 2*DD; ldb = HM;
    }
    const int K = LL, nkt = 17;
    int tid = threadIdx.x;
    int n0 = blockIdx.x * 64, m0 = blockIdx.y * 64;

    int akr = tid >> 4, amq = (tid & 15) * 4;
    int bkr = tid >> 4, bnq = (tid & 15) * 4;

    auto readAr = [&](int kt, float* ar) {
        int kr = kt*16 + akr;
        if (kr < K) {
            float4 v = *(const float4*)(A + (long)kr*lda + m0 + amq);
            ar[0]=v.x; ar[1]=v.y; ar[2]=v.z; ar[3]=v.w;
        } else { ar[0]=ar[1]=ar[2]=ar[3]=0.f; }
    };
    auto readBr = [&](int kt, float* br) {
        int kr = kt*16 + bkr;
        if (kr < K) {
            float4 v = *(const float4*)(B + (long)kr*ldb + n0 + bnq);
            br[0]=v.x; br[1]=v.y; br[2]=v.z; br[3]=v.w;
        } else { br[0]=br[1]=br[2]=br[3]=0.f; }
    };
    auto storeAr = [&](int buf, const float* ar) {
        #pragma unroll
        for (int j = 0; j < 4; j++) {
            __nv_bfloat16 h, l;
            split1(ar[j], h, l);
            AsH[buf][amq+j][akr] = h;
            AsL[buf][amq+j][akr] = l;
        }
    };
    auto storeBr = [&](int buf, const float* br) {
        #pragma unroll
        for (int j = 0; j < 4; j++) {
            __nv_bfloat16 h, l;
            split1(br[j], h, l);
            BsH[buf][bnq+j][bkr] = h;
            BsL[buf][bnq+j][bkr] = l;
        }
    };

    int warp = tid >> 5, lane = tid & 31;
    int wm = warp & 1, wn = warp >> 1;
    int g = lane >> 2, tq = lane & 3;
    int ko = tq * 2;
    float acc[2][2][4] = {};
    float csum = 0.f;

    auto mma_on = [&](int cur) {
        unsigned ah[2][4], al[2][4], bh[2][2], bl[2][2];
        #pragma unroll
        for (int mi = 0; mi < 2; mi++) {
            int r = wm*32 + mi*16 + g;
            ah[mi][0] = *(const unsigned*)&AsH[cur][r][ko];
            ah[mi][1] = *(const unsigned*)&AsH[cur][r+8][ko];
            ah[mi][2] = *(const unsigned*)&AsH[cur][r][ko+8];
            ah[mi][3] = *(const unsigned*)&AsH[cur][r+8][ko+8];
            al[mi][0] = *(const unsigned*)&AsL[cur][r][ko];
            al[mi][1] = *(const unsigned*)&AsL[cur][r+8][ko];
            al[mi][2] = *(const unsigned*)&AsL[cur][r][ko+8];
            al[mi][3] = *(const unsigned*)&AsL[cur][r+8][ko+8];
        }
        #pragma unroll
        for (int ni = 0; ni < 2; ni++) {
            int nr = wn*16 + ni*8 + g;
            bh[ni][0] = *(const unsigned*)&BsH[cur][nr][ko];
            bh[ni][1] = *(const unsigned*)&BsH[cur][nr][ko+8];
            bl[ni][0] = *(const unsigned*)&BsL[cur][nr][ko];
            bl[ni][1] = *(const unsigned*)&BsL[cur][nr][ko+8];
        }
        if (tid < 64) {
            #pragma unroll
            for (int k2 = 0; k2 < 16; k2 += 2) {
                float2 hf = __bfloat1622float2(*(const __nv_bfloat162*)&BsH[cur][tid][k2]);
                float2 lf = __bfloat1622float2(*(const __nv_bfloat162*)&BsL[cur][tid][k2]);
                csum += hf.x + hf.y + lf.x + lf.y;
            }
        }
        #pragma unroll
        for (int mi = 0; mi < 2; mi++)
            #pragma unroll
            for (int ni = 0; ni < 2; ni++) {
                MMA_BF16(acc[mi][ni], ah[mi], bh[ni]);
                MMA_BF16(acc[mi][ni], al[mi], bh[ni]);
                MMA_BF16(acc[mi][ni], ah[mi], bl[ni]);
            }
    };

    float a0[4], b0r[4], a1[4], b1r[4];
    readAr(0, a0); readBr(0, b0r);
    storeAr(0, a0); storeBr(0, b0r);
    readAr(1, a1); readBr(1, b1r);
    __syncthreads();
    int kt = 0;
    while (true) {
        if (kt + 2 < nkt) { readAr(kt+2, a0); readBr(kt+2, b0r); }
        mma_on(kt & 1);
        if (kt + 1 < nkt) { storeAr((kt+1) & 1, a1); storeBr((kt+1) & 1, b1r); }
        __syncthreads();
        if (++kt >= nkt) break;
        if (kt + 2 < nkt) { readAr(kt+2, a1); readBr(kt+2, b1r); }
        mma_on(kt & 1);
        if (kt + 1 < nkt) { storeAr((kt+1) & 1, a0); storeBr((kt+1) & 1, b0r); }
        __syncthreads();
        if (++kt >= nkt) break;
    }

    float alpha = g_coef[b*3+0], eta = g_coef[b*3+1], theta = g_coef[b*3+2];

    if (blockIdx.y == 0 && tid < 64) {
        int idx = n0 + tid;
        float m = eta * mbp[idx] - theta * csum;
        mbp[idx] = m;
        fbp[idx] = (1.f - alpha) * fbp[idx] + m;
    }

    #pragma unroll
    for (int mi = 0; mi < 2; mi++)
        #pragma unroll
        for (int ni = 0; ni < 2; ni++) {
            int c0 = n0 + wn*16 + ni*8 + tq*2;
            #pragma unroll
            for (int h2 = 0; h2 < 2; h2++) {
                int r = m0 + wm*32 + mi*16 + g + h2*8;
                long i0 = (long)r*256 + c0;
                float m0v = eta * mp[i0]   - theta * acc[mi][ni][h2*2+0];
                float m1v = eta * mp[i0+1] - theta * acc[mi][ni][h2*2+1];
                mp[i0]   = m0v;
                mp[i0+1] = m1v;
                fp[i0]   = (1.f - alpha) * fp[i0]   + m0v;
                fp[i0+1] = (1.f - alpha) * fp[i0+1] + m1v;
            }
        }
}

// ---------------- attention: block = (b, head, 8-row tile), smem K/V -------
__global__ void k_attn2() {
    __shared__ float Ks[64][33];
    __shared__ float Vs[64][33];
    __shared__ float qs[8][32];
    __shared__ float ps[8][32];
    int blk = blockIdx.x;
    int tile = blk % (LL/8);
    int hh = (blk / (LL/8)) % NH;
    int b  = blk / ((LL/8)*NH);
    int rt0 = tile * 8;
    int tid = threadIdx.x;
    int w = tid >> 5, lane = tid & 31;
    int r = rt0 + w;
    const float* base = g_qkv + (long)b*LL*3*DD;
    qs[w][lane] = base[(long)r*3*DD + hh*HD + lane] * 0.17677669529663687f;
    float m = -1e30f, l = 0.f, o = 0.f;
    int ntile = (rt0 + 71) >> 6;
    int krow = tid >> 3;
    int kc = (tid & 7) * 4;
    for (int jt = 0; jt < ntile; jt++) {
        int j0 = jt * 64;
        __syncthreads();
        #pragma unroll
        for (int half = 0; half < 2; half++) {
            int jl = krow + half*32;
            int jg = j0 + jl; if (jg > LL-1) jg = LL-1;
            const float* kp = base + (long)jg*3*DD + DD + hh*HD + kc;
            float4 k4 = *(const float4*)kp;
            float4 v4 = *(const float4*)(kp + DD);
            Ks[jl][kc]=k4.x; Ks[jl][kc+1]=k4.y; Ks[jl][kc+2]=k4.z; Ks[jl][kc+3]=k4.w;
            Vs[jl][kc]=v4.x; Vs[jl][kc+1]=v4.y; Vs[jl][kc+2]=v4.z; Vs[jl][kc+3]=v4.w;
        }
        __syncthreads();
        #pragma unroll
        for (int c = 0; c < 2; c++) {
            int jbase = j0 + c*32;
            if (jbase > r) break;
            int jl = c*32 + lane;
            int jg = jbase + lane;
            float sc = 0.f;
            #pragma unroll
            for (int d = 0; d < 32; d++) sc += qs[w][d] * Ks[jl][d];
            if (jg > r) sc = -1e30f;
            float cm = sc;
            #pragma unroll
            for (int s = 16; s; s >>= 1) cm = fmaxf(cm, __shfl_xor_sync(0xffffffffu, cm, s));
            float mn = fmaxf(m, cm);
            float p = (jg <= r) ? expf(sc - mn) : 0.f;
            __syncwarp();
            ps[w][lane] = p;
            float psum = p;
            #pragma unroll
            for (int s = 16; s; s >>= 1) psum += __shfl_xor_sync(0xffffffffu, psum, s);
            float corr = expf(m - mn);
            l = l*corr + psum; o *= corr; m = mn;
            __syncwarp();
            int jmax = min(32, r - jbase + 1);
            for (int jj = 0; jj < jmax; jj++)
                o += ps[w][jj] * Vs[c*32 + jj][lane];
        }
    }
    g_ao[((long)b*LL + r)*DD + hh*HD + lane] = o / l;
}

// ---------------- gate coefficients (1024 threads, 4-way token split) ------
__global__ void k_coef(const float* __restrict__ cW1, const float* __restrict__ cb1,
                       const float* __restrict__ cW2, const float* __restrict__ cb2) {
    int b = blockIdx.x, tid = threadIdx.x;
    __shared__ float part[4][DD];
    __shared__ float ybar[DD];
    __shared__ float ch[CHN];
    int col = tid & 255, p = tid >> 8;     // 4 partitions x 66 tokens
    const float* yp = g_y + (long)b*LL*DD + col;
    float sum = 0.f;
    for (int t = p*66; t < (p+1)*66; t++) sum += yp[(long)t*DD];
    part[p][col] = sum;
    __syncthreads();
    if (tid < DD)
        ybar[tid] = (part[0][tid] + part[1][tid] + part[2][tid] + part[3][tid]) / (float)LL;
    __syncthreads();
    if (tid < CHN) {
        float a = cb1[tid];
        for (int d = 0; d < DD; d++) a += ybar[d] * cW1[d*CHN + tid];
        ch[tid] = a / (1.f + expf(-a));
    }
    __syncthreads();
    if (tid < 3) {
        float a = cb2[tid];
        for (int j = 0; j < CHN; j++) a += ch[j] * cW2[j*3 + tid];
        g_coef[b*3 + tid] = 1.f / (1.f + expf(-a));
    }
}

// ---------------------------------------------------------------------------
extern "C" void kernel_launch(void* const* d_in, const int* in_sizes, int n_in,
                              void* d_out, int out_size) {
    const float* x     = (const float*)d_in[0];
    const float* pers  = (const float*)d_in[1];
    const float* W_Q   = (const float*)d_in[2];
    const float* in_w  = (const float*)d_in[3];
    const float* in_b  = (const float*)d_in[4];
    const float* out_w = (const float*)d_in[5];
    const float* out_b = (const float*)d_in[6];
    const float* mW1   = (const float*)d_in[7];
    const float* mb1   = (const float*)d_in[8];
    const float* mW2   = (const float*)d_in[9];
    const float* mb2   = (const float*)d_in[10];
    const float* W_K   = (const float*)d_in[11];
    const float* W_V   = (const float*)d_in[12];
    const float* cW1   = (const float*)d_in[13];
    const float* cb1   = (const float*)d_in[14];
    const float* cW2   = (const float*)d_in[15];
    const float* cb2   = (const float*)d_in[16];
    float* out = (float*)d_out;

    cudaFuncSetAttribute(k_mlp_single, cudaFuncAttributeMaxDynamicSharedMemorySize, SMEM_MLP);
    cudaFuncSetAttribute(k_mlp_dual,   cudaFuncAttributeMaxDynamicSharedMemorySize, SMEM_MLP);

    // side stream + events for taking k_coef off the critical path
    static cudaStream_t sSide = nullptr;
    static cudaEvent_t evY = nullptr, evC = nullptr;
    if (sSide == nullptr) {
        cudaStreamCreateWithFlags(&sSide, cudaStreamNonBlocking);
        cudaEventCreateWithFlags(&evY, cudaEventDisableTiming);
        cudaEventCreateWithFlags(&evC, cudaEventDisableTiming);
    }

    float *pQall, *pWkv, *pAttnA, *pQkv, *pAo, *pY, *pKV, *pS, *pDz, *pE;
    cudaGetSymbolAddress((void**)&pQall, g_qall);
    cudaGetSymbolAddress((void**)&pWkv, g_Wkv);
    cudaGetSymbolAddress((void**)&pAttnA, g_attnA);
    cudaGetSymbolAddress((void**)&pQkv, g_qkv);
    cudaGetSymbolAddress((void**)&pAo, g_ao);
    cudaGetSymbolAddress((void**)&pY, g_y);
    cudaGetSymbolAddress((void**)&pKV, g_kv);
    cudaGetSymbolAddress((void**)&pS, g_s);
    cudaGetSymbolAddress((void**)&pDz, g_dz);
    cudaGetSymbolAddress((void**)&pE, g_e);

    k_init<<<((long)BB*DD*HM + 255)/256, 256>>>(mW1, mb1, mW2, mb2, W_K, W_V);
    k_prepack<<<((long)NSEG*BB*(PP+CC)*DD + 255)/256, 256>>>(x, pers);

    // Q_all = x @ W_Q  (M = 32768)
    t_gemm<false,false><<<dim3(DD/64, (BB*SS)/64, 1), 256>>>(
        x, W_Q, nullptr, pQall, BB*SS, DD, DD, DD, DD, DD, 0L, 0L, 0L, 0);

    // h(0) = silu(q(0) @ W1 + b1) @ W2 + b2
    k_mlp_single<<<dim3(1, CC/MROWS, BB), 256, SMEM_MLP>>>(
        0, pQall, pAttnA + PP*DD, nullptr, nullptr, nullptr,
        CC, DD, (long)SS*DD, (long)LL*DD);

    const int LT = (LL + MROWS - 1) / MROWS;   // 9
    for (int s = 0; s < NSEG; s++) {
        int s0 = s * CC;
        float* pAttnS = pAttnA + (long)s*BB*LL*DD;

        // qkv = attn_in @ in_proj_w^T + in_proj_b  (M = 4224)
        t_gemm<true,true><<<dim3((3*DD)/64, (BB*LL)/64, 1), 256>>>(
            pAttnS, in_w, in_b, pQkv, BB*LL, 3*DD, DD, DD, DD, 3*DD, 0L, 0L, 0L, 0);
        k_attn2<<<BB*NH*(LL/8), 256>>>();
        // y = ao @ out_proj_w^T + out_proj_b
        t_gemm<true,true><<<dim3(DD/64, (BB*LL)/64, 1), 256>>>(
            pAo, out_w, out_b, pY, BB*LL, DD, DD, DD, DD, DD, 0L, 0L, 0L, 0);

        // fork: coef runs on side stream, off the critical path
        cudaEventRecord(evY, 0);
        cudaStreamWaitEvent(sSide, evY, 0);
        k_coef<<<BB, 1024, 0, sSide>>>(cW1, cb1, cW2, cb2);
        cudaEventRecord(evC, sSide);

        // [k|v] = y @ Wkv   (main stream continues immediately)
        t_gemm<false,false><<<dim3((2*DD)/64, (BB*LL)/64, 1), 256>>>(
            pY, pWkv, nullptr, pKV, BB*LL, 2*DD, DD, DD, 2*DD, 2*DD, 0L, 0L, 0L, 0);

        // fused grad: z, s, e, dz   (9 x 16 = 144 blocks)
        k_mlp_single<<<dim3(1, LT, BB), 256, SMEM_MLP>>>(
            1, pKV, pS, pE, pDz, pKV + DD,
            LL, 2*DD, (long)LL*2*DD, (long)LL*HM);

        // join coef before the weight update
        cudaStreamWaitEvent(0, evC, 0);
        // gW2/gW1 tiles + fused momentum/decay weight update (one launch)
        k_grad<<<dim3(4, 4, 2*BB), 256>>>();

        if (s < NSEG-1) {
            // fused: out(s) = y_last * mem_apply(y_last)  AND  h(s+1)
            k_mlp_dual<<<dim3(1, CC/MROWS, 2*BB), 256, SMEM_MLP>>>(
                pY + (long)(PP+CC)*DD, out + (long)s0*DD,
                pQall + (long)(s0+CC)*DD, pAttnA + (long)(s+1)*BB*LL*DD + PP*DD,
                (long)LL*DD, (long)SS*DD, (long)SS*DD, (long)LL*DD);
        } else {
            k_mlp_single<<<dim3(1, CC/MROWS, BB), 256, SMEM_MLP>>>(
                2, pY + (long)(PP+CC)*DD, out + (long)s0*DD, nullptr, nullptr, nullptr,
                CC, DD, (long)LL*DD, (long)SS*DD);
        }
    }
}